// round 1
// baseline (speedup 1.0000x reference)
#include <cuda_runtime.h>
#include <cuda_bf16.h>
#include <cstddef>

// Problem constants
#define NN     50000
#define EE     800000
#define TOT_E  (EE + NN)          // edges + self loops = 850000
#define INC    256
#define HIDC   128
#define OUTC   128
#define NEG_SLOPE 0.2f

// ---------------------------------------------------------------------------
// Scratch (device globals; no cudaMalloc allowed)
// ---------------------------------------------------------------------------
__device__ __align__(16) float g_h1[(size_t)NN * 256];    // layer1 linear out
__device__ __align__(16) float g_out1[(size_t)NN * 256];  // layer1 final (post ELU)
__device__ __align__(16) float g_h2[(size_t)NN * 128];    // layer2 linear out
__device__ float g_as1[NN * 2];
__device__ float g_ad1[NN * 2];
__device__ float g_as2[NN];
__device__ float g_ad2[NN];
__device__ int   g_cnt[NN];       // per-dst degree (incl. self loop)
__device__ int   g_cur[NN];       // scatter cursor
__device__ int   g_rowptr[NN + 1];
__device__ int   g_esrc[TOT_E];   // CSR: sources grouped by dst

// ---------------------------------------------------------------------------
// CSR build: histogram -> scan -> scatter
// ---------------------------------------------------------------------------
__global__ void k_init_cnt() {
    int i = blockIdx.x * blockDim.x + threadIdx.x;
    if (i < NN) g_cnt[i] = 1;     // self loop
}

__global__ void k_hist(const int* __restrict__ dst) {
    int i = blockIdx.x * blockDim.x + threadIdx.x;
    if (i < EE) atomicAdd(&g_cnt[dst[i]], 1);
}

__global__ void k_scan() {
    // single block, 1024 threads, two-pass chunked scan over NN counts
    const int T = 1024;
    __shared__ int sums[T];
    int tid = threadIdx.x;
    int chunk = (NN + T - 1) / T;                  // 49
    int begin = tid * chunk;
    int end   = begin + chunk; if (end > NN) end = NN;
    int s = 0;
    for (int i = begin; i < end; i++) s += g_cnt[i];
    sums[tid] = s;
    __syncthreads();
    // Hillis-Steele inclusive scan
    for (int off = 1; off < T; off <<= 1) {
        int v = 0;
        if (tid >= off) v = sums[tid - off];
        __syncthreads();
        sums[tid] += v;
        __syncthreads();
    }
    int base = (tid == 0) ? 0 : sums[tid - 1];     // exclusive prefix
    for (int i = begin; i < end; i++) {
        g_rowptr[i] = base;
        g_cur[i]    = base;
        base += g_cnt[i];
    }
    if (tid == T - 1) g_rowptr[NN] = base;
}

__global__ void k_scatter(const int* __restrict__ src, const int* __restrict__ dst) {
    int i = blockIdx.x * blockDim.x + threadIdx.x;
    if (i < EE) {
        int p = atomicAdd(&g_cur[dst[i]], 1);
        g_esrc[p] = src[i];
    } else if (i < TOT_E) {
        int n = i - EE;                            // self loop n -> n
        int p = atomicAdd(&g_cur[n], 1);
        g_esrc[p] = n;
    }
}

// ---------------------------------------------------------------------------
// SGEMM: C[M,Ncols] = A[M,K] @ B[K,Ncols], row-major, fp32
// BM=BN=64, BK=16, 256 threads, 4x4 per-thread microtile
// ---------------------------------------------------------------------------
__global__ __launch_bounds__(256) void k_sgemm(const float* __restrict__ A,
                                               const float* __restrict__ B,
                                               float* __restrict__ C,
                                               int M, int Ncols, int K)
{
    const int BM = 64, BN = 64, BK = 16;
    __shared__ float As[BK][BM + 4];   // transposed A tile, padded
    __shared__ float Bs[BK][BN];

    int tid = threadIdx.x;
    int tx = tid & 15;         // 0..15 -> col group
    int ty = tid >> 4;         // 0..15 -> row group
    int rowBlock = blockIdx.y * BM;
    int colBlock = blockIdx.x * BN;

    int arow = tid >> 2;               // 0..63
    int ak   = (tid & 3) * 4;          // 0,4,8,12
    int brow = tid >> 4;               // 0..15
    int bcol = (tid & 15) * 4;         // 0..60

    float acc[4][4];
#pragma unroll
    for (int i = 0; i < 4; i++)
#pragma unroll
        for (int j = 0; j < 4; j++) acc[i][j] = 0.f;

    for (int kt = 0; kt < K; kt += BK) {
        float4 a4 = make_float4(0.f, 0.f, 0.f, 0.f);
        int gr = rowBlock + arow;
        if (gr < M) a4 = *(const float4*)(A + (size_t)gr * K + kt + ak);
        As[ak + 0][arow] = a4.x;
        As[ak + 1][arow] = a4.y;
        As[ak + 2][arow] = a4.z;
        As[ak + 3][arow] = a4.w;

        float4 b4 = *(const float4*)(B + (size_t)(kt + brow) * Ncols + colBlock + bcol);
        *(float4*)&Bs[brow][bcol] = b4;
        __syncthreads();

#pragma unroll
        for (int kk = 0; kk < BK; kk++) {
            float4 av = *(const float4*)&As[kk][ty * 4];
            float4 bv = *(const float4*)&Bs[kk][tx * 4];
            float a[4] = {av.x, av.y, av.z, av.w};
            float b[4] = {bv.x, bv.y, bv.z, bv.w};
#pragma unroll
            for (int i = 0; i < 4; i++)
#pragma unroll
                for (int j = 0; j < 4; j++) acc[i][j] += a[i] * b[j];
        }
        __syncthreads();
    }

#pragma unroll
    for (int i = 0; i < 4; i++) {
        int gr = rowBlock + ty * 4 + i;
        if (gr < M) {
            float4 o = make_float4(acc[i][0], acc[i][1], acc[i][2], acc[i][3]);
            *(float4*)(C + (size_t)gr * Ncols + colBlock + tx * 4) = o;
        }
    }
}

// ---------------------------------------------------------------------------
// Alpha dot products: as[n,h] = h[n,h,:] . a_s[h,:], ad likewise (C=128)
// one warp per (node, head)
// ---------------------------------------------------------------------------
__device__ __forceinline__ float warp_sum(float v) {
#pragma unroll
    for (int o = 16; o; o >>= 1) v += __shfl_xor_sync(0xFFFFFFFFu, v, o);
    return v;
}

__global__ void k_alpha(const float* __restrict__ h,
                        const float* __restrict__ a_s,
                        const float* __restrict__ a_d,
                        float* __restrict__ out_s,
                        float* __restrict__ out_d,
                        int H)
{
    int g = blockIdx.x * blockDim.x + threadIdx.x;
    int w = g >> 5, lane = g & 31;
    int node = w / H, head = w - node * H;
    if (node >= NN) return;
    const float4* hv = (const float4*)(h + ((size_t)node * H + head) * 128);
    float4 x  = hv[lane];
    float4 s4 = ((const float4*)(a_s + head * 128))[lane];
    float4 d4 = ((const float4*)(a_d + head * 128))[lane];
    float ss = x.x * s4.x + x.y * s4.y + x.z * s4.z + x.w * s4.w;
    float sd = x.x * d4.x + x.y * d4.y + x.z * d4.z + x.w * d4.w;
    ss = warp_sum(ss);
    sd = warp_sum(sd);
    if (lane == 0) {
        out_s[node * H + head] = ss;
        out_d[node * H + head] = sd;
    }
}

// ---------------------------------------------------------------------------
// Aggregation (softmax over incoming edges + weighted sum), one warp per node
// ---------------------------------------------------------------------------
__device__ __forceinline__ float lrelu(float x) { return x > 0.f ? x : NEG_SLOPE * x; }
__device__ __forceinline__ float eluf(float x)  { return x > 0.f ? x : (__expf(x) - 1.f); }

// Layer 1: H=2, C=128 per head, features 256. out1 = elu(agg + b1)
__global__ __launch_bounds__(256) void k_agg1(const float* __restrict__ b1)
{
    int w = (blockIdx.x * blockDim.x + threadIdx.x) >> 5;
    int lane = threadIdx.x & 31;
    if (w >= NN) return;
    int node = w;
    int beg = g_rowptr[node], end = g_rowptr[node + 1];
    float ad0 = g_ad1[2 * node], ad1v = g_ad1[2 * node + 1];

    // pass 1: per-head max over neighborhood
    float m0 = -1e30f, m1 = -1e30f;
    for (int t = beg + lane; t < end; t += 32) {
        int s = g_esrc[t];
        m0 = fmaxf(m0, lrelu(g_as1[2 * s] + ad0));
        m1 = fmaxf(m1, lrelu(g_as1[2 * s + 1] + ad1v));
    }
#pragma unroll
    for (int o = 16; o; o >>= 1) {
        m0 = fmaxf(m0, __shfl_xor_sync(0xFFFFFFFFu, m0, o));
        m1 = fmaxf(m1, __shfl_xor_sync(0xFFFFFFFFu, m1, o));
    }

    // pass 2: acc = sum w_j * h_j, denom = sum w_j  (softmax folded into final divide)
    float4 acc0 = make_float4(0.f, 0.f, 0.f, 0.f);
    float4 acc1 = make_float4(0.f, 0.f, 0.f, 0.f);
    float d0 = 0.f, d1 = 0.f;
    const float4* hbase = (const float4*)g_h1;     // row stride 64 float4
    for (int t = beg; t < end; t++) {
        int s = g_esrc[t];
        float w0 = __expf(lrelu(g_as1[2 * s]     + ad0)  - m0);
        float w1 = __expf(lrelu(g_as1[2 * s + 1] + ad1v) - m1);
        d0 += w0; d1 += w1;
        float4 h0 = hbase[(size_t)s * 64 + lane];
        float4 hb = hbase[(size_t)s * 64 + 32 + lane];
        acc0.x += w0 * h0.x; acc0.y += w0 * h0.y; acc0.z += w0 * h0.z; acc0.w += w0 * h0.w;
        acc1.x += w1 * hb.x; acc1.y += w1 * hb.y; acc1.z += w1 * hb.z; acc1.w += w1 * hb.w;
    }
    float inv0 = 1.f / d0, inv1 = 1.f / d1;
    float4 bb0 = ((const float4*)b1)[lane];
    float4 bb1 = ((const float4*)b1)[32 + lane];
    float4 o0, o1;
    o0.x = eluf(acc0.x * inv0 + bb0.x);
    o0.y = eluf(acc0.y * inv0 + bb0.y);
    o0.z = eluf(acc0.z * inv0 + bb0.z);
    o0.w = eluf(acc0.w * inv0 + bb0.w);
    o1.x = eluf(acc1.x * inv1 + bb1.x);
    o1.y = eluf(acc1.y * inv1 + bb1.y);
    o1.z = eluf(acc1.z * inv1 + bb1.z);
    o1.w = eluf(acc1.w * inv1 + bb1.w);
    ((float4*)g_out1)[(size_t)node * 64 + lane]      = o0;
    ((float4*)g_out1)[(size_t)node * 64 + 32 + lane] = o1;
}

// Layer 2: H=1, C=128. out = agg + b2 (no activation), written to d_out.
__global__ __launch_bounds__(256) void k_agg2(const float* __restrict__ b2,
                                              float* __restrict__ out)
{
    int w = (blockIdx.x * blockDim.x + threadIdx.x) >> 5;
    int lane = threadIdx.x & 31;
    if (w >= NN) return;
    int node = w;
    int beg = g_rowptr[node], end = g_rowptr[node + 1];
    float ad = g_ad2[node];

    float m = -1e30f;
    for (int t = beg + lane; t < end; t += 32) {
        int s = g_esrc[t];
        m = fmaxf(m, lrelu(g_as2[s] + ad));
    }
#pragma unroll
    for (int o = 16; o; o >>= 1) m = fmaxf(m, __shfl_xor_sync(0xFFFFFFFFu, m, o));

    float4 acc = make_float4(0.f, 0.f, 0.f, 0.f);
    float d = 0.f;
    const float4* hbase = (const float4*)g_h2;     // row stride 32 float4
    for (int t = beg; t < end; t++) {
        int s = g_esrc[t];
        float wv = __expf(lrelu(g_as2[s] + ad) - m);
        d += wv;
        float4 hv = hbase[(size_t)s * 32 + lane];
        acc.x += wv * hv.x; acc.y += wv * hv.y; acc.z += wv * hv.z; acc.w += wv * hv.w;
    }
    float inv = 1.f / d;
    float4 bb = ((const float4*)b2)[lane];
    float4 o;
    o.x = acc.x * inv + bb.x;
    o.y = acc.y * inv + bb.y;
    o.z = acc.z * inv + bb.z;
    o.w = acc.w * inv + bb.w;
    ((float4*)out)[(size_t)node * 32 + lane] = o;
}

// ---------------------------------------------------------------------------
// Launch
// ---------------------------------------------------------------------------
extern "C" void kernel_launch(void* const* d_in, const int* in_sizes, int n_in,
                              void* d_out, int out_size)
{
    const float* x      = (const float*)d_in[0];
    const int*   eidx   = (const int*)d_in[1];
    const float* W1     = (const float*)d_in[2];
    const float* a_src1 = (const float*)d_in[3];
    const float* a_dst1 = (const float*)d_in[4];
    const float* b1     = (const float*)d_in[5];
    const float* W2     = (const float*)d_in[6];
    const float* a_src2 = (const float*)d_in[7];
    const float* a_dst2 = (const float*)d_in[8];
    const float* b2     = (const float*)d_in[9];
    float* out = (float*)d_out;

    const int* e_src = eidx;
    const int* e_dst = eidx + EE;

    float* p_h1   = nullptr; cudaGetSymbolAddress((void**)&p_h1,   g_h1);
    float* p_out1 = nullptr; cudaGetSymbolAddress((void**)&p_out1, g_out1);
    float* p_h2   = nullptr; cudaGetSymbolAddress((void**)&p_h2,   g_h2);
    float* p_as1  = nullptr; cudaGetSymbolAddress((void**)&p_as1,  g_as1);
    float* p_ad1  = nullptr; cudaGetSymbolAddress((void**)&p_ad1,  g_ad1);
    float* p_as2  = nullptr; cudaGetSymbolAddress((void**)&p_as2,  g_as2);
    float* p_ad2  = nullptr; cudaGetSymbolAddress((void**)&p_ad2,  g_ad2);

    // --- CSR build (reused for both layers) ---
    k_init_cnt<<<(NN + 255) / 256, 256>>>();
    k_hist<<<(EE + 255) / 256, 256>>>(e_dst);
    k_scan<<<1, 1024>>>();
    k_scatter<<<(TOT_E + 255) / 256, 256>>>(e_src, e_dst);

    // --- Layer 1 ---
    {
        dim3 grid(256 / 64, (NN + 63) / 64);
        k_sgemm<<<grid, 256>>>(x, W1, p_h1, NN, 256, INC);
    }
    {
        int warps = NN * 2;
        k_alpha<<<(warps * 32 + 255) / 256, 256>>>(p_h1, a_src1, a_dst1, p_as1, p_ad1, 2);
    }
    k_agg1<<<(NN * 32 + 255) / 256, 256>>>(b1);

    // --- Layer 2 ---
    {
        dim3 grid(128 / 64, (NN + 63) / 64);
        k_sgemm<<<grid, 256>>>(p_out1, W2, p_h2, NN, 128, 2 * HIDC);
    }
    {
        int warps = NN;
        k_alpha<<<(warps * 32 + 255) / 256, 256>>>(p_h2, a_src2, a_dst2, p_as2, p_ad2, 1);
    }
    k_agg2<<<(NN * 32 + 255) / 256, 256>>>(b2, out);
}

// round 3
// speedup vs baseline: 1.1986x; 1.1986x over previous
#include <cuda_runtime.h>
#include <cuda_bf16.h>
#include <cstdint>
#include <cstddef>

// Problem constants
#define NN     50000
#define EE     800000
#define TOT_E  (EE + NN)          // edges + self loops = 850000
#define INC    256
#define HIDC   128
#define OUTC   128
#define NEG_SLOPE 0.2f
#define GRID_M ((NN + 127) / 128) // 391

// ---------------------------------------------------------------------------
// Portable async-copy / mma helpers (sm_80+; safe for plain compute_100)
// ---------------------------------------------------------------------------
__device__ __forceinline__ uint32_t smem_u32(const void* p) {
    uint32_t a;
    asm("{ .reg .u64 t; cvta.to.shared.u64 t, %1; cvt.u32.u64 %0, t; }" : "=r"(a) : "l"(p));
    return a;
}
#define CP_ASYNC16(dst, src) \
    asm volatile("cp.async.cg.shared.global [%0], [%1], 16;" :: "r"(dst), "l"(src))
#define CP_COMMIT() asm volatile("cp.async.commit_group;" ::: "memory")
#define CP_WAIT1()  asm volatile("cp.async.wait_group 1;" ::: "memory")
#define CP_WAIT0()  asm volatile("cp.async.wait_group 0;" ::: "memory")

#define LDMATRIX_X4(r0, r1, r2, r3, addr) \
    asm volatile("ldmatrix.sync.aligned.m8n8.x4.shared.b16 {%0,%1,%2,%3}, [%4];" \
        : "=r"(r0), "=r"(r1), "=r"(r2), "=r"(r3) : "r"(addr))

#define MMA_BF16(c0, c1, c2, c3, a0, a1, a2, a3, b0, b1) \
    asm volatile("mma.sync.aligned.m16n8k16.row.col.f32.bf16.bf16.f32 " \
        "{%0,%1,%2,%3}, {%4,%5,%6,%7}, {%8,%9}, {%0,%1,%2,%3};" \
        : "+f"(c0), "+f"(c1), "+f"(c2), "+f"(c3) \
        : "r"(a0), "r"(a1), "r"(a2), "r"(a3), "r"(b0), "r"(b1))

// ---------------------------------------------------------------------------
// Scratch (device globals; no cudaMalloc allowed)
// ---------------------------------------------------------------------------
__device__ __align__(16) float g_h1[(size_t)NN * 256];    // layer1 linear out (fp32)
__device__ __align__(16) float g_h2[(size_t)NN * 128];    // layer2 linear out (fp32)
__device__ __align__(16) __nv_bfloat16 g_xhi[(size_t)NN * 256];
__device__ __align__(16) __nv_bfloat16 g_xlo[(size_t)NN * 256];
__device__ __align__(16) __nv_bfloat16 g_a2hi[(size_t)NN * 256];  // out1 hi
__device__ __align__(16) __nv_bfloat16 g_a2lo[(size_t)NN * 256];  // out1 lo
__device__ __align__(16) __nv_bfloat16 g_B1[256 * 512];   // W1 ext: [n][k_ext] hi|lo
__device__ __align__(16) __nv_bfloat16 g_B2[128 * 512];   // W2 ext
__device__ float g_as1[NN * 2];
__device__ float g_ad1[NN * 2];
__device__ float g_as2[NN];
__device__ float g_ad2[NN];
__device__ int   g_cnt[NN];
__device__ int   g_cur[NN];
__device__ int   g_rowptr[NN + 1];
__device__ int   g_esrc[TOT_E];

// ---------------------------------------------------------------------------
// CSR build: histogram -> scan -> scatter
// ---------------------------------------------------------------------------
__global__ void k_init_cnt() {
    int i = blockIdx.x * blockDim.x + threadIdx.x;
    if (i < NN) g_cnt[i] = 1;
}
__global__ void k_hist(const int* __restrict__ dst) {
    int i = blockIdx.x * blockDim.x + threadIdx.x;
    if (i < EE) atomicAdd(&g_cnt[dst[i]], 1);
}
__global__ void k_scan() {
    const int T = 1024;
    __shared__ int sums[T];
    int tid = threadIdx.x;
    int chunk = (NN + T - 1) / T;
    int begin = tid * chunk;
    int end   = begin + chunk; if (end > NN) end = NN;
    int s = 0;
    for (int i = begin; i < end; i++) s += g_cnt[i];
    sums[tid] = s;
    __syncthreads();
    for (int off = 1; off < T; off <<= 1) {
        int v = 0;
        if (tid >= off) v = sums[tid - off];
        __syncthreads();
        sums[tid] += v;
        __syncthreads();
    }
    int base = (tid == 0) ? 0 : sums[tid - 1];
    for (int i = begin; i < end; i++) {
        g_rowptr[i] = base;
        g_cur[i]    = base;
        base += g_cnt[i];
    }
    if (tid == T - 1) g_rowptr[NN] = base;
}
__global__ void k_scatter(const int* __restrict__ src, const int* __restrict__ dst) {
    int i = blockIdx.x * blockDim.x + threadIdx.x;
    if (i < EE) {
        int p = atomicAdd(&g_cur[dst[i]], 1);
        g_esrc[p] = src[i];
    } else if (i < TOT_E) {
        int n = i - EE;
        int p = atomicAdd(&g_cur[n], 1);
        g_esrc[p] = n;
    }
}

// ---------------------------------------------------------------------------
// Precision-split prep kernels
// ---------------------------------------------------------------------------
__global__ void k_split_x(const float* __restrict__ x) {
    size_t i = (size_t)blockIdx.x * blockDim.x + threadIdx.x;
    if (i >= (size_t)NN * 256) return;
    float v = x[i];
    __nv_bfloat16 h = __float2bfloat16(v);
    g_xhi[i] = h;
    g_xlo[i] = __float2bfloat16(v - __bfloat162float(h));
}
// W [K=256 rows][Ncols] fp32 -> Bext [Ncols rows][512]: cols 0..255 = hi, 256..511 = lo
__global__ void k_prep_w(const float* __restrict__ W, __nv_bfloat16* __restrict__ Bext, int Ncols) {
    int i = blockIdx.x * blockDim.x + threadIdx.x;
    if (i >= 256 * Ncols) return;
    int k = i / Ncols, n = i - k * Ncols;
    float v = W[i];
    __nv_bfloat16 h = __float2bfloat16(v);
    Bext[(size_t)n * 512 + k]       = h;
    Bext[(size_t)n * 512 + 256 + k] = __float2bfloat16(v - __bfloat162float(h));
}

// ---------------------------------------------------------------------------
// bf16x3 mma.sync GEMM: C[M, NCOLS] = (Ahi+Alo)[M,256] @ Bext^T
// virtual K = 768 (seg0 hi*hi, seg1 lo*hi, seg2 hi*lo)
// CTA tile 128x128, BK=32, 8 warps (warp tile 64m x 32n), cp.async dbl-buffer
// ---------------------------------------------------------------------------
#define BK   32
#define PADK 40   // padded row length (80B: 8 distinct 16B banks for ldmatrix)
#define NCHUNK 24 // 3 segments * 8 chunks of 32

template <int NCOLS>
__global__ __launch_bounds__(256) void k_gemm_mma(const __nv_bfloat16* __restrict__ Ahi,
                                                  const __nv_bfloat16* __restrict__ Alo,
                                                  const __nv_bfloat16* __restrict__ Bext,
                                                  float* __restrict__ C, int M)
{
    __shared__ __nv_bfloat16 As[2][128][PADK];
    __shared__ __nv_bfloat16 Bs[2][128][PADK];

    const int tid  = threadIdx.x;
    const int wid  = tid >> 5;
    const int lane = tid & 31;
    const int warpM = wid & 1;      // 2 x 64 rows
    const int warpN = wid >> 1;     // 4 x 32 cols
    const int rowBlock = blockIdx.y * 128;
    const int colBlock = blockIdx.x * 128;

    const uint32_t as_base = smem_u32(&As[0][0][0]);
    const uint32_t bs_base = smem_u32(&Bs[0][0][0]);
    const uint32_t BUF = 128 * PADK * 2;  // bytes per buffer

    // per-thread load coords: 512 16B-granules per tile, 2 per thread
    const int lrow0 = tid >> 1;                 // 0..127
    const int lcol0 = (tid & 1) * 16;           // 0 or 16 (elements)

    float c[4][4][4];
#pragma unroll
    for (int i = 0; i < 4; i++)
#pragma unroll
        for (int j = 0; j < 4; j++)
#pragma unroll
            for (int q = 0; q < 4; q++) c[i][j][q] = 0.f;

    auto load_chunk = [&](int cidx) {
        int buf = cidx & 1;
        int seg = cidx >> 3, kin = (cidx & 7) * BK;
        const __nv_bfloat16* Asrc = (seg == 1) ? Alo : Ahi;
        int bcol = (seg == 2) ? 256 + kin : kin;
        // A: rows lrow0, cols lcol0..+15 (two 16B each thread)
        int gr = rowBlock + lrow0; if (gr >= M) gr = M - 1;
#pragma unroll
        for (int h = 0; h < 2; h++) {
            uint32_t d = as_base + buf * BUF + ((lrow0)*PADK + lcol0 + h * 8) * 2;
            CP_ASYNC16(d, Asrc + (size_t)gr * 256 + kin + lcol0 + h * 8);
        }
        // B: rows (n) lrow0 within this col block
        int gn = colBlock + lrow0;
#pragma unroll
        for (int h = 0; h < 2; h++) {
            uint32_t d = bs_base + buf * BUF + ((lrow0)*PADK + lcol0 + h * 8) * 2;
            CP_ASYNC16(d, Bext + (size_t)gn * 512 + bcol + lcol0 + h * 8);
        }
    };

    load_chunk(0);
    CP_COMMIT();

    for (int cidx = 0; cidx < NCHUNK; cidx++) {
        if (cidx + 1 < NCHUNK) {
            load_chunk(cidx + 1);
            CP_COMMIT();
            CP_WAIT1();
        } else {
            CP_WAIT0();
        }
        __syncthreads();

        int buf = cidx & 1;
        uint32_t abase = as_base + buf * BUF;
        uint32_t bbase = bs_base + buf * BUF;

#pragma unroll
        for (int k16 = 0; k16 < 2; k16++) {
            int k0 = k16 * 16;
            // B fragments: 8 regs cover n-tile of 32 at this k16
            uint32_t b[8];
#pragma unroll
            for (int np = 0; np < 2; np++) {
                int n0 = warpN * 32 + np * 16;
                int mat = lane >> 3;
                int row = n0 + ((mat >> 1) << 3) + (lane & 7);
                int col = k0 + ((mat & 1) << 3);
                uint32_t addr = bbase + (row * PADK + col) * 2;
                LDMATRIX_X4(b[np * 4 + 0], b[np * 4 + 1], b[np * 4 + 2], b[np * 4 + 3], addr);
            }
#pragma unroll
            for (int mt = 0; mt < 4; mt++) {
                int m0 = warpM * 64 + mt * 16;
                int row = m0 + (lane & 15);
                int col = k0 + ((lane >> 4) << 3);
                uint32_t addr = abase + (row * PADK + col) * 2;
                uint32_t a0, a1, a2, a3;
                LDMATRIX_X4(a0, a1, a2, a3, addr);
#pragma unroll
                for (int nt = 0; nt < 4; nt++) {
                    MMA_BF16(c[mt][nt][0], c[mt][nt][1], c[mt][nt][2], c[mt][nt][3],
                             a0, a1, a2, a3, b[nt * 2], b[nt * 2 + 1]);
                }
            }
        }
        __syncthreads();
    }

    // epilogue
#pragma unroll
    for (int mt = 0; mt < 4; mt++) {
        int r0 = rowBlock + warpM * 64 + mt * 16 + (lane >> 2);
#pragma unroll
        for (int nt = 0; nt < 4; nt++) {
            int cg = colBlock + warpN * 32 + nt * 8 + 2 * (lane & 3);
            if (r0 < M)
                *(float2*)(C + (size_t)r0 * NCOLS + cg) = make_float2(c[mt][nt][0], c[mt][nt][1]);
            if (r0 + 8 < M)
                *(float2*)(C + (size_t)(r0 + 8) * NCOLS + cg) = make_float2(c[mt][nt][2], c[mt][nt][3]);
        }
    }
}

// ---------------------------------------------------------------------------
// Alpha dot products
// ---------------------------------------------------------------------------
__device__ __forceinline__ float warp_sum(float v) {
#pragma unroll
    for (int o = 16; o; o >>= 1) v += __shfl_xor_sync(0xFFFFFFFFu, v, o);
    return v;
}
__global__ void k_alpha(const float* __restrict__ h,
                        const float* __restrict__ a_s,
                        const float* __restrict__ a_d,
                        float* __restrict__ out_s,
                        float* __restrict__ out_d,
                        int H)
{
    int g = blockIdx.x * blockDim.x + threadIdx.x;
    int w = g >> 5, lane = g & 31;
    int node = w / H, head = w - node * H;
    if (node >= NN) return;
    const float4* hv = (const float4*)(h + ((size_t)node * H + head) * 128);
    float4 x  = hv[lane];
    float4 s4 = ((const float4*)(a_s + head * 128))[lane];
    float4 d4 = ((const float4*)(a_d + head * 128))[lane];
    float ss = x.x * s4.x + x.y * s4.y + x.z * s4.z + x.w * s4.w;
    float sd = x.x * d4.x + x.y * d4.y + x.z * d4.z + x.w * d4.w;
    ss = warp_sum(ss);
    sd = warp_sum(sd);
    if (lane == 0) {
        out_s[node * H + head] = ss;
        out_d[node * H + head] = sd;
    }
}

// ---------------------------------------------------------------------------
// Aggregation
// ---------------------------------------------------------------------------
__device__ __forceinline__ float lrelu(float x) { return x > 0.f ? x : NEG_SLOPE * x; }
__device__ __forceinline__ float eluf(float x)  { return x > 0.f ? x : (__expf(x) - 1.f); }

__device__ __forceinline__ void store4_hilo(__nv_bfloat16* hi, __nv_bfloat16* lo,
                                            size_t off, float4 v) {
    __nv_bfloat16 h0 = __float2bfloat16(v.x), h1 = __float2bfloat16(v.y);
    __nv_bfloat16 h2 = __float2bfloat16(v.z), h3 = __float2bfloat16(v.w);
    __nv_bfloat16 l0 = __float2bfloat16(v.x - __bfloat162float(h0));
    __nv_bfloat16 l1 = __float2bfloat16(v.y - __bfloat162float(h1));
    __nv_bfloat16 l2 = __float2bfloat16(v.z - __bfloat162float(h2));
    __nv_bfloat16 l3 = __float2bfloat16(v.w - __bfloat162float(h3));
    __nv_bfloat162 a, b, cc, d;
    a.x = h0; a.y = h1; b.x = h2; b.y = h3;
    cc.x = l0; cc.y = l1; d.x = l2; d.y = l3;
    *(__nv_bfloat162*)(hi + off)     = a;
    *(__nv_bfloat162*)(hi + off + 2) = b;
    *(__nv_bfloat162*)(lo + off)     = cc;
    *(__nv_bfloat162*)(lo + off + 2) = d;
}

// Layer 1: H=2, C=128/head. out1 = elu(agg + b1), stored as bf16 hi/lo for GEMM2.
__global__ __launch_bounds__(256) void k_agg1(const float* __restrict__ b1)
{
    int w = (blockIdx.x * blockDim.x + threadIdx.x) >> 5;
    int lane = threadIdx.x & 31;
    if (w >= NN) return;
    int node = w;
    int beg = g_rowptr[node], end = g_rowptr[node + 1];
    float ad0 = g_ad1[2 * node], ad1v = g_ad1[2 * node + 1];

    float m0 = -1e30f, m1 = -1e30f;
    for (int t = beg + lane; t < end; t += 32) {
        int s = g_esrc[t];
        m0 = fmaxf(m0, lrelu(g_as1[2 * s] + ad0));
        m1 = fmaxf(m1, lrelu(g_as1[2 * s + 1] + ad1v));
    }
#pragma unroll
    for (int o = 16; o; o >>= 1) {
        m0 = fmaxf(m0, __shfl_xor_sync(0xFFFFFFFFu, m0, o));
        m1 = fmaxf(m1, __shfl_xor_sync(0xFFFFFFFFu, m1, o));
    }

    float4 acc0 = make_float4(0.f, 0.f, 0.f, 0.f);
    float4 acc1 = make_float4(0.f, 0.f, 0.f, 0.f);
    float d0 = 0.f, d1 = 0.f;
    const float4* hbase = (const float4*)g_h1;
    for (int t = beg; t < end; t++) {
        int s = g_esrc[t];
        float w0 = __expf(lrelu(g_as1[2 * s]     + ad0)  - m0);
        float w1 = __expf(lrelu(g_as1[2 * s + 1] + ad1v) - m1);
        d0 += w0; d1 += w1;
        float4 h0 = hbase[(size_t)s * 64 + lane];
        float4 hb = hbase[(size_t)s * 64 + 32 + lane];
        acc0.x += w0 * h0.x; acc0.y += w0 * h0.y; acc0.z += w0 * h0.z; acc0.w += w0 * h0.w;
        acc1.x += w1 * hb.x; acc1.y += w1 * hb.y; acc1.z += w1 * hb.z; acc1.w += w1 * hb.w;
    }
    float inv0 = 1.f / d0, inv1 = 1.f / d1;
    float4 bb0 = ((const float4*)b1)[lane];
    float4 bb1 = ((const float4*)b1)[32 + lane];
    float4 o0, o1;
    o0.x = eluf(acc0.x * inv0 + bb0.x);
    o0.y = eluf(acc0.y * inv0 + bb0.y);
    o0.z = eluf(acc0.z * inv0 + bb0.z);
    o0.w = eluf(acc0.w * inv0 + bb0.w);
    o1.x = eluf(acc1.x * inv1 + bb1.x);
    o1.y = eluf(acc1.y * inv1 + bb1.y);
    o1.z = eluf(acc1.z * inv1 + bb1.z);
    o1.w = eluf(acc1.w * inv1 + bb1.w);
    store4_hilo(g_a2hi, g_a2lo, (size_t)node * 256 + lane * 4, o0);
    store4_hilo(g_a2hi, g_a2lo, (size_t)node * 256 + 128 + lane * 4, o1);
}

// Layer 2: H=1, C=128. out = agg + b2 -> d_out.
__global__ __launch_bounds__(256) void k_agg2(const float* __restrict__ b2,
                                              float* __restrict__ out)
{
    int w = (blockIdx.x * blockDim.x + threadIdx.x) >> 5;
    int lane = threadIdx.x & 31;
    if (w >= NN) return;
    int node = w;
    int beg = g_rowptr[node], end = g_rowptr[node + 1];
    float ad = g_ad2[node];

    float m = -1e30f;
    for (int t = beg + lane; t < end; t += 32) {
        int s = g_esrc[t];
        m = fmaxf(m, lrelu(g_as2[s] + ad));
    }
#pragma unroll
    for (int o = 16; o; o >>= 1) m = fmaxf(m, __shfl_xor_sync(0xFFFFFFFFu, m, o));

    float4 acc = make_float4(0.f, 0.f, 0.f, 0.f);
    float d = 0.f;
    const float4* hbase = (const float4*)g_h2;
    for (int t = beg; t < end; t++) {
        int s = g_esrc[t];
        float wv = __expf(lrelu(g_as2[s] + ad) - m);
        d += wv;
        float4 hv = hbase[(size_t)s * 32 + lane];
        acc.x += wv * hv.x; acc.y += wv * hv.y; acc.z += wv * hv.z; acc.w += wv * hv.w;
    }
    float inv = 1.f / d;
    float4 bb = ((const float4*)b2)[lane];
    float4 o;
    o.x = acc.x * inv + bb.x;
    o.y = acc.y * inv + bb.y;
    o.z = acc.z * inv + bb.z;
    o.w = acc.w * inv + bb.w;
    ((float4*)out)[(size_t)node * 32 + lane] = o;
}

// ---------------------------------------------------------------------------
// Launch
// ---------------------------------------------------------------------------
extern "C" void kernel_launch(void* const* d_in, const int* in_sizes, int n_in,
                              void* d_out, int out_size)
{
    const float* x      = (const float*)d_in[0];
    const int*   eidx   = (const int*)d_in[1];
    const float* W1     = (const float*)d_in[2];
    const float* a_src1 = (const float*)d_in[3];
    const float* a_dst1 = (const float*)d_in[4];
    const float* b1     = (const float*)d_in[5];
    const float* W2     = (const float*)d_in[6];
    const float* a_src2 = (const float*)d_in[7];
    const float* a_dst2 = (const float*)d_in[8];
    const float* b2     = (const float*)d_in[9];
    float* out = (float*)d_out;

    const int* e_src = eidx;
    const int* e_dst = eidx + EE;

    float* p_h1  = nullptr; cudaGetSymbolAddress((void**)&p_h1,  g_h1);
    float* p_h2  = nullptr; cudaGetSymbolAddress((void**)&p_h2,  g_h2);
    float* p_as1 = nullptr; cudaGetSymbolAddress((void**)&p_as1, g_as1);
    float* p_ad1 = nullptr; cudaGetSymbolAddress((void**)&p_ad1, g_ad1);
    float* p_as2 = nullptr; cudaGetSymbolAddress((void**)&p_as2, g_as2);
    float* p_ad2 = nullptr; cudaGetSymbolAddress((void**)&p_ad2, g_ad2);
    __nv_bfloat16 *p_xhi, *p_xlo, *p_a2hi, *p_a2lo, *p_B1, *p_B2;
    cudaGetSymbolAddress((void**)&p_xhi,  g_xhi);
    cudaGetSymbolAddress((void**)&p_xlo,  g_xlo);
    cudaGetSymbolAddress((void**)&p_a2hi, g_a2hi);
    cudaGetSymbolAddress((void**)&p_a2lo, g_a2lo);
    cudaGetSymbolAddress((void**)&p_B1,   g_B1);
    cudaGetSymbolAddress((void**)&p_B2,   g_B2);

    // --- prep: precision split + W transpose ---
    k_split_x<<<(NN * 256 + 255) / 256, 256>>>(x);
    k_prep_w<<<(256 * 256 + 255) / 256, 256>>>(W1, p_B1, 256);
    k_prep_w<<<(256 * 128 + 255) / 256, 256>>>(W2, p_B2, 128);

    // --- CSR build ---
    k_init_cnt<<<(NN + 255) / 256, 256>>>();
    k_hist<<<(EE + 255) / 256, 256>>>(e_dst);
    k_scan<<<1, 1024>>>();
    k_scatter<<<(TOT_E + 255) / 256, 256>>>(e_src, e_dst);

    // --- Layer 1 ---
    {
        dim3 grid(256 / 128, GRID_M);
        k_gemm_mma<256><<<grid, 256>>>(p_xhi, p_xlo, p_B1, p_h1, NN);
    }
    k_alpha<<<(NN * 2 * 32 + 255) / 256, 256>>>(p_h1, a_src1, a_dst1, p_as1, p_ad1, 2);
    k_agg1<<<(NN * 32 + 255) / 256, 256>>>(b1);

    // --- Layer 2 ---
    {
        dim3 grid(128 / 128, GRID_M);
        k_gemm_mma<128><<<grid, 256>>>(p_a2hi, p_a2lo, p_B2, p_h2, NN);
    }
    k_alpha<<<(NN * 32 + 255) / 256, 256>>>(p_h2, a_src2, a_dst2, p_as2, p_ad2, 1);
    k_agg2<<<(NN * 32 + 255) / 256, 256>>>(b2, out);
}

// round 4
// speedup vs baseline: 1.3012x; 1.0856x over previous
#include <cuda_runtime.h>
#include <cuda_bf16.h>
#include <cstdint>
#include <cstddef>

// Problem constants
#define NN     50000
#define EE     800000
#define TOT_E  (EE + NN)          // edges + self loops = 850000
#define INC    256
#define HIDC   128
#define OUTC   128
#define NEG_SLOPE 0.2f
#define GRID_M ((NN + 127) / 128) // 391

// ---------------------------------------------------------------------------
// Portable async-copy / mma helpers (sm_80+; safe for plain compute_100)
// ---------------------------------------------------------------------------
__device__ __forceinline__ uint32_t smem_u32(const void* p) {
    uint32_t a;
    asm("{ .reg .u64 t; cvta.to.shared.u64 t, %1; cvt.u32.u64 %0, t; }" : "=r"(a) : "l"(p));
    return a;
}
#define CP_ASYNC16(dst, src) \
    asm volatile("cp.async.cg.shared.global [%0], [%1], 16;" :: "r"(dst), "l"(src))
#define CP_COMMIT() asm volatile("cp.async.commit_group;" ::: "memory")
#define CP_WAIT1()  asm volatile("cp.async.wait_group 1;" ::: "memory")
#define CP_WAIT0()  asm volatile("cp.async.wait_group 0;" ::: "memory")

#define LDMATRIX_X4(r0, r1, r2, r3, addr) \
    asm volatile("ldmatrix.sync.aligned.m8n8.x4.shared.b16 {%0,%1,%2,%3}, [%4];" \
        : "=r"(r0), "=r"(r1), "=r"(r2), "=r"(r3) : "r"(addr))

#define MMA_BF16(c0, c1, c2, c3, a0, a1, a2, a3, b0, b1) \
    asm volatile("mma.sync.aligned.m16n8k16.row.col.f32.bf16.bf16.f32 " \
        "{%0,%1,%2,%3}, {%4,%5,%6,%7}, {%8,%9}, {%0,%1,%2,%3};" \
        : "+f"(c0), "+f"(c1), "+f"(c2), "+f"(c3) \
        : "r"(a0), "r"(a1), "r"(a2), "r"(a3), "r"(b0), "r"(b1))

// ---------------------------------------------------------------------------
// Scratch (device globals; no cudaMalloc allowed)
// ---------------------------------------------------------------------------
__device__ __align__(16) float g_h1[(size_t)NN * 256];    // layer1 linear out (fp32)
__device__ __align__(16) float g_h2[(size_t)NN * 128];    // layer2 linear out (fp32)
__device__ __align__(16) __nv_bfloat16 g_xhi[(size_t)NN * 256];
__device__ __align__(16) __nv_bfloat16 g_xlo[(size_t)NN * 256];
__device__ __align__(16) __nv_bfloat16 g_a2hi[(size_t)NN * 256];  // out1 hi
__device__ __align__(16) __nv_bfloat16 g_a2lo[(size_t)NN * 256];  // out1 lo
__device__ __align__(16) __nv_bfloat16 g_B1[256 * 512];   // W1 ext: [n][k_ext] hi|lo
__device__ __align__(16) __nv_bfloat16 g_B2[128 * 512];   // W2 ext
__device__ float g_as1[NN * 2];
__device__ float g_ad1[NN * 2];
__device__ float g_as2[NN];
__device__ float g_ad2[NN];
__device__ int   g_cnt[NN];
__device__ int   g_cur[NN];
__device__ int   g_rowptr[NN + 1];
__device__ int   g_esrc[TOT_E];

// ---------------------------------------------------------------------------
// CSR build: histogram -> scan -> scatter
// ---------------------------------------------------------------------------
__global__ void k_init_cnt() {
    int i = blockIdx.x * blockDim.x + threadIdx.x;
    if (i < NN) g_cnt[i] = 1;
}
__global__ void k_hist(const int* __restrict__ dst) {
    int i = blockIdx.x * blockDim.x + threadIdx.x;
    if (i < EE) atomicAdd(&g_cnt[dst[i]], 1);
}
__global__ void k_scan() {
    const int T = 1024;
    __shared__ int sums[T];
    int tid = threadIdx.x;
    int chunk = (NN + T - 1) / T;
    int begin = tid * chunk;
    int end   = begin + chunk; if (end > NN) end = NN;
    int s = 0;
    for (int i = begin; i < end; i++) s += g_cnt[i];
    sums[tid] = s;
    __syncthreads();
    for (int off = 1; off < T; off <<= 1) {
        int v = 0;
        if (tid >= off) v = sums[tid - off];
        __syncthreads();
        sums[tid] += v;
        __syncthreads();
    }
    int base = (tid == 0) ? 0 : sums[tid - 1];
    for (int i = begin; i < end; i++) {
        g_rowptr[i] = base;
        g_cur[i]    = base;
        base += g_cnt[i];
    }
    if (tid == T - 1) g_rowptr[NN] = base;
}
__global__ void k_scatter(const int* __restrict__ src, const int* __restrict__ dst) {
    int i = blockIdx.x * blockDim.x + threadIdx.x;
    if (i < EE) {
        int p = atomicAdd(&g_cur[dst[i]], 1);
        g_esrc[p] = src[i];
    } else if (i < TOT_E) {
        int n = i - EE;
        int p = atomicAdd(&g_cur[n], 1);
        g_esrc[p] = n;
    }
}

// ---------------------------------------------------------------------------
// Precision-split prep kernels
// ---------------------------------------------------------------------------
__global__ void k_split_x(const float* __restrict__ x) {
    size_t i = (size_t)blockIdx.x * blockDim.x + threadIdx.x;
    if (i >= (size_t)NN * 256) return;
    float v = x[i];
    __nv_bfloat16 h = __float2bfloat16(v);
    g_xhi[i] = h;
    g_xlo[i] = __float2bfloat16(v - __bfloat162float(h));
}
// W [K=256 rows][Ncols] fp32 -> Bext [Ncols rows][512]: cols 0..255 = hi, 256..511 = lo
__global__ void k_prep_w(const float* __restrict__ W, __nv_bfloat16* __restrict__ Bext, int Ncols) {
    int i = blockIdx.x * blockDim.x + threadIdx.x;
    if (i >= 256 * Ncols) return;
    int k = i / Ncols, n = i - k * Ncols;
    float v = W[i];
    __nv_bfloat16 h = __float2bfloat16(v);
    Bext[(size_t)n * 512 + k]       = h;
    Bext[(size_t)n * 512 + 256 + k] = __float2bfloat16(v - __bfloat162float(h));
}

// ---------------------------------------------------------------------------
// bf16x3 mma.sync GEMM with shared-tile scheme:
//   per K-chunk (BK=32) load {A_hi, A_lo, B_hi, B_lo} ONCE, issue
//   hi*hi + lo*hi + hi*lo from registers.
// CTA tile 128x128, 8 warps (warp tile 64m x 32n), cp.async double buffer.
// Dynamic smem: 4 tiles x 2 buffers x (128 x PADK bf16) = 81,920 B.
// ---------------------------------------------------------------------------
#define BK     32
#define PADK   40                  // 80B rows: ldmatrix row addrs hit 8 distinct 16B banks
#define TILE_B (128 * PADK * 2)    // 10240 bytes per tile
#define NCHUNK 8                   // 256 / BK

template <int NCOLS>
__global__ __launch_bounds__(256) void k_gemm3(const __nv_bfloat16* __restrict__ Ahi,
                                               const __nv_bfloat16* __restrict__ Alo,
                                               const __nv_bfloat16* __restrict__ Bext,
                                               float* __restrict__ C, int M)
{
    extern __shared__ __align__(16) char smem[];
    // tile order per buffer slot: [buf][tile], tile: 0=Ahi 1=Alo 2=Bhi 3=Blo
    const uint32_t sb = smem_u32(smem);

    const int tid  = threadIdx.x;
    const int wid  = tid >> 5;
    const int lane = tid & 31;
    const int warpM = wid & 1;      // 2 x 64 rows
    const int warpN = wid >> 1;     // 4 x 32 cols
    const int rowBlock = blockIdx.y * 128;
    const int colBlock = blockIdx.x * 128;

    // per-thread load coords (per tile): 512 granules of 16B, 2 per thread
    const int lrow = tid >> 1;            // 0..127
    const int lcol = (tid & 1) * 16;      // 0 or 16

    int gr = rowBlock + lrow; if (gr >= M) gr = M - 1;
    const int gn = colBlock + lrow;
    const __nv_bfloat16* aHiP = Ahi + (size_t)gr * 256 + lcol;
    const __nv_bfloat16* aLoP = Alo + (size_t)gr * 256 + lcol;
    const __nv_bfloat16* bHiP = Bext + (size_t)gn * 512 + lcol;
    const __nv_bfloat16* bLoP = Bext + (size_t)gn * 512 + 256 + lcol;

    float c[4][4][4];
#pragma unroll
    for (int i = 0; i < 4; i++)
#pragma unroll
        for (int j = 0; j < 4; j++)
#pragma unroll
            for (int q = 0; q < 4; q++) c[i][j][q] = 0.f;

    auto load_chunk = [&](int cidx) {
        const int buf = cidx & 1;
        const int kin = cidx * BK;
        const uint32_t base = sb + buf * (4 * TILE_B) + (lrow * PADK + lcol) * 2;
#pragma unroll
        for (int h = 0; h < 2; h++) {
            CP_ASYNC16(base + 0 * TILE_B + h * 16, aHiP + kin + h * 8);
            CP_ASYNC16(base + 1 * TILE_B + h * 16, aLoP + kin + h * 8);
            CP_ASYNC16(base + 2 * TILE_B + h * 16, bHiP + kin + h * 8);
            CP_ASYNC16(base + 3 * TILE_B + h * 16, bLoP + kin + h * 8);
        }
    };

    load_chunk(0);
    CP_COMMIT();

    for (int cidx = 0; cidx < NCHUNK; cidx++) {
        if (cidx + 1 < NCHUNK) {
            load_chunk(cidx + 1);
            CP_COMMIT();
            CP_WAIT1();
        } else {
            CP_WAIT0();
        }
        __syncthreads();

        const int buf = cidx & 1;
        const uint32_t tAhi = sb + buf * (4 * TILE_B) + 0 * TILE_B;
        const uint32_t tAlo = sb + buf * (4 * TILE_B) + 1 * TILE_B;
        const uint32_t tBhi = sb + buf * (4 * TILE_B) + 2 * TILE_B;
        const uint32_t tBlo = sb + buf * (4 * TILE_B) + 3 * TILE_B;

#pragma unroll
        for (int k16 = 0; k16 < 2; k16++) {
            const int k0 = k16 * 16;

            // B fragments for this warp's 32-col slab
            uint32_t bhi[8], blo[8];
#pragma unroll
            for (int np = 0; np < 2; np++) {
                const int n0 = warpN * 32 + np * 16;
                const int mat = lane >> 3;
                const int row = n0 + ((mat >> 1) << 3) + (lane & 7);
                const int col = k0 + ((mat & 1) << 3);
                const uint32_t off = (row * PADK + col) * 2;
                LDMATRIX_X4(bhi[np*4+0], bhi[np*4+1], bhi[np*4+2], bhi[np*4+3], tBhi + off);
                LDMATRIX_X4(blo[np*4+0], blo[np*4+1], blo[np*4+2], blo[np*4+3], tBlo + off);
            }
            // A fragments for this warp's 64-row slab
            uint32_t ahi[4][4], alo[4][4];
#pragma unroll
            for (int mt = 0; mt < 4; mt++) {
                const int m0 = warpM * 64 + mt * 16;
                const int row = m0 + (lane & 15);
                const int col = k0 + ((lane >> 4) << 3);
                const uint32_t off = (row * PADK + col) * 2;
                LDMATRIX_X4(ahi[mt][0], ahi[mt][1], ahi[mt][2], ahi[mt][3], tAhi + off);
                LDMATRIX_X4(alo[mt][0], alo[mt][1], alo[mt][2], alo[mt][3], tAlo + off);
            }
            // three products, all accumulating
#pragma unroll
            for (int mt = 0; mt < 4; mt++) {
#pragma unroll
                for (int nt = 0; nt < 4; nt++) {
                    MMA_BF16(c[mt][nt][0], c[mt][nt][1], c[mt][nt][2], c[mt][nt][3],
                             ahi[mt][0], ahi[mt][1], ahi[mt][2], ahi[mt][3],
                             bhi[nt*2], bhi[nt*2+1]);
                    MMA_BF16(c[mt][nt][0], c[mt][nt][1], c[mt][nt][2], c[mt][nt][3],
                             alo[mt][0], alo[mt][1], alo[mt][2], alo[mt][3],
                             bhi[nt*2], bhi[nt*2+1]);
                    MMA_BF16(c[mt][nt][0], c[mt][nt][1], c[mt][nt][2], c[mt][nt][3],
                             ahi[mt][0], ahi[mt][1], ahi[mt][2], ahi[mt][3],
                             blo[nt*2], blo[nt*2+1]);
                }
            }
        }
        __syncthreads();
    }

    // epilogue
#pragma unroll
    for (int mt = 0; mt < 4; mt++) {
        int r0 = rowBlock + warpM * 64 + mt * 16 + (lane >> 2);
#pragma unroll
        for (int nt = 0; nt < 4; nt++) {
            int cg = colBlock + warpN * 32 + nt * 8 + 2 * (lane & 3);
            if (r0 < M)
                *(float2*)(C + (size_t)r0 * NCOLS + cg) = make_float2(c[mt][nt][0], c[mt][nt][1]);
            if (r0 + 8 < M)
                *(float2*)(C + (size_t)(r0 + 8) * NCOLS + cg) = make_float2(c[mt][nt][2], c[mt][nt][3]);
        }
    }
}

// ---------------------------------------------------------------------------
// Alpha dot products
// ---------------------------------------------------------------------------
__device__ __forceinline__ float warp_sum(float v) {
#pragma unroll
    for (int o = 16; o; o >>= 1) v += __shfl_xor_sync(0xFFFFFFFFu, v, o);
    return v;
}
__global__ void k_alpha(const float* __restrict__ h,
                        const float* __restrict__ a_s,
                        const float* __restrict__ a_d,
                        float* __restrict__ out_s,
                        float* __restrict__ out_d,
                        int H)
{
    int g = blockIdx.x * blockDim.x + threadIdx.x;
    int w = g >> 5, lane = g & 31;
    int node = w / H, head = w - node * H;
    if (node >= NN) return;
    const float4* hv = (const float4*)(h + ((size_t)node * H + head) * 128);
    float4 x  = hv[lane];
    float4 s4 = ((const float4*)(a_s + head * 128))[lane];
    float4 d4 = ((const float4*)(a_d + head * 128))[lane];
    float ss = x.x * s4.x + x.y * s4.y + x.z * s4.z + x.w * s4.w;
    float sd = x.x * d4.x + x.y * d4.y + x.z * d4.z + x.w * d4.w;
    ss = warp_sum(ss);
    sd = warp_sum(sd);
    if (lane == 0) {
        out_s[node * H + head] = ss;
        out_d[node * H + head] = sd;
    }
}

// ---------------------------------------------------------------------------
// Aggregation
// ---------------------------------------------------------------------------
__device__ __forceinline__ float lrelu(float x) { return x > 0.f ? x : NEG_SLOPE * x; }
__device__ __forceinline__ float eluf(float x)  { return x > 0.f ? x : (__expf(x) - 1.f); }

__device__ __forceinline__ void store4_hilo(__nv_bfloat16* hi, __nv_bfloat16* lo,
                                            size_t off, float4 v) {
    __nv_bfloat16 h0 = __float2bfloat16(v.x), h1 = __float2bfloat16(v.y);
    __nv_bfloat16 h2 = __float2bfloat16(v.z), h3 = __float2bfloat16(v.w);
    __nv_bfloat16 l0 = __float2bfloat16(v.x - __bfloat162float(h0));
    __nv_bfloat16 l1 = __float2bfloat16(v.y - __bfloat162float(h1));
    __nv_bfloat16 l2 = __float2bfloat16(v.z - __bfloat162float(h2));
    __nv_bfloat16 l3 = __float2bfloat16(v.w - __bfloat162float(h3));
    __nv_bfloat162 a, b, cc, d;
    a.x = h0; a.y = h1; b.x = h2; b.y = h3;
    cc.x = l0; cc.y = l1; d.x = l2; d.y = l3;
    *(__nv_bfloat162*)(hi + off)     = a;
    *(__nv_bfloat162*)(hi + off + 2) = b;
    *(__nv_bfloat162*)(lo + off)     = cc;
    *(__nv_bfloat162*)(lo + off + 2) = d;
}

// Layer 1: H=2, C=128/head. out1 = elu(agg + b1), stored as bf16 hi/lo for GEMM2.
__global__ __launch_bounds__(256) void k_agg1(const float* __restrict__ b1)
{
    int w = (blockIdx.x * blockDim.x + threadIdx.x) >> 5;
    int lane = threadIdx.x & 31;
    if (w >= NN) return;
    int node = w;
    int beg = g_rowptr[node], end = g_rowptr[node + 1];
    float ad0 = g_ad1[2 * node], ad1v = g_ad1[2 * node + 1];

    float m0 = -1e30f, m1 = -1e30f;
    for (int t = beg + lane; t < end; t += 32) {
        int s = g_esrc[t];
        m0 = fmaxf(m0, lrelu(g_as1[2 * s] + ad0));
        m1 = fmaxf(m1, lrelu(g_as1[2 * s + 1] + ad1v));
    }
#pragma unroll
    for (int o = 16; o; o >>= 1) {
        m0 = fmaxf(m0, __shfl_xor_sync(0xFFFFFFFFu, m0, o));
        m1 = fmaxf(m1, __shfl_xor_sync(0xFFFFFFFFu, m1, o));
    }

    float4 acc0 = make_float4(0.f, 0.f, 0.f, 0.f);
    float4 acc1 = make_float4(0.f, 0.f, 0.f, 0.f);
    float d0 = 0.f, d1 = 0.f;
    const float4* hbase = (const float4*)g_h1;
    for (int t = beg; t < end; t++) {
        int s = g_esrc[t];
        float w0 = __expf(lrelu(g_as1[2 * s]     + ad0)  - m0);
        float w1 = __expf(lrelu(g_as1[2 * s + 1] + ad1v) - m1);
        d0 += w0; d1 += w1;
        float4 h0 = hbase[(size_t)s * 64 + lane];
        float4 hb = hbase[(size_t)s * 64 + 32 + lane];
        acc0.x += w0 * h0.x; acc0.y += w0 * h0.y; acc0.z += w0 * h0.z; acc0.w += w0 * h0.w;
        acc1.x += w1 * hb.x; acc1.y += w1 * hb.y; acc1.z += w1 * hb.z; acc1.w += w1 * hb.w;
    }
    float inv0 = 1.f / d0, inv1 = 1.f / d1;
    float4 bb0 = ((const float4*)b1)[lane];
    float4 bb1 = ((const float4*)b1)[32 + lane];
    float4 o0, o1;
    o0.x = eluf(acc0.x * inv0 + bb0.x);
    o0.y = eluf(acc0.y * inv0 + bb0.y);
    o0.z = eluf(acc0.z * inv0 + bb0.z);
    o0.w = eluf(acc0.w * inv0 + bb0.w);
    o1.x = eluf(acc1.x * inv1 + bb1.x);
    o1.y = eluf(acc1.y * inv1 + bb1.y);
    o1.z = eluf(acc1.z * inv1 + bb1.z);
    o1.w = eluf(acc1.w * inv1 + bb1.w);
    store4_hilo(g_a2hi, g_a2lo, (size_t)node * 256 + lane * 4, o0);
    store4_hilo(g_a2hi, g_a2lo, (size_t)node * 256 + 128 + lane * 4, o1);
}

// Layer 2: H=1, C=128. out = agg + b2 -> d_out.
__global__ __launch_bounds__(256) void k_agg2(const float* __restrict__ b2,
                                              float* __restrict__ out)
{
    int w = (blockIdx.x * blockDim.x + threadIdx.x) >> 5;
    int lane = threadIdx.x & 31;
    if (w >= NN) return;
    int node = w;
    int beg = g_rowptr[node], end = g_rowptr[node + 1];
    float ad = g_ad2[node];

    float m = -1e30f;
    for (int t = beg + lane; t < end; t += 32) {
        int s = g_esrc[t];
        m = fmaxf(m, lrelu(g_as2[s] + ad));
    }
#pragma unroll
    for (int o = 16; o; o >>= 1) m = fmaxf(m, __shfl_xor_sync(0xFFFFFFFFu, m, o));

    float4 acc = make_float4(0.f, 0.f, 0.f, 0.f);
    float d = 0.f;
    const float4* hbase = (const float4*)g_h2;
    for (int t = beg; t < end; t++) {
        int s = g_esrc[t];
        float wv = __expf(lrelu(g_as2[s] + ad) - m);
        d += wv;
        float4 hv = hbase[(size_t)s * 32 + lane];
        acc.x += wv * hv.x; acc.y += wv * hv.y; acc.z += wv * hv.z; acc.w += wv * hv.w;
    }
    float inv = 1.f / d;
    float4 bb = ((const float4*)b2)[lane];
    float4 o;
    o.x = acc.x * inv + bb.x;
    o.y = acc.y * inv + bb.y;
    o.z = acc.z * inv + bb.z;
    o.w = acc.w * inv + bb.w;
    ((float4*)out)[(size_t)node * 32 + lane] = o;
}

// ---------------------------------------------------------------------------
// Launch  (GEMM1 placed as 4th launch so the profiler captures it)
// ---------------------------------------------------------------------------
extern "C" void kernel_launch(void* const* d_in, const int* in_sizes, int n_in,
                              void* d_out, int out_size)
{
    const float* x      = (const float*)d_in[0];
    const int*   eidx   = (const int*)d_in[1];
    const float* W1     = (const float*)d_in[2];
    const float* a_src1 = (const float*)d_in[3];
    const float* a_dst1 = (const float*)d_in[4];
    const float* b1     = (const float*)d_in[5];
    const float* W2     = (const float*)d_in[6];
    const float* a_src2 = (const float*)d_in[7];
    const float* a_dst2 = (const float*)d_in[8];
    const float* b2     = (const float*)d_in[9];
    float* out = (float*)d_out;

    const int* e_src = eidx;
    const int* e_dst = eidx + EE;

    float* p_h1  = nullptr; cudaGetSymbolAddress((void**)&p_h1,  g_h1);
    float* p_h2  = nullptr; cudaGetSymbolAddress((void**)&p_h2,  g_h2);
    float* p_as1 = nullptr; cudaGetSymbolAddress((void**)&p_as1, g_as1);
    float* p_ad1 = nullptr; cudaGetSymbolAddress((void**)&p_ad1, g_ad1);
    float* p_as2 = nullptr; cudaGetSymbolAddress((void**)&p_as2, g_as2);
    float* p_ad2 = nullptr; cudaGetSymbolAddress((void**)&p_ad2, g_ad2);
    __nv_bfloat16 *p_xhi, *p_xlo, *p_a2hi, *p_a2lo, *p_B1, *p_B2;
    cudaGetSymbolAddress((void**)&p_xhi,  g_xhi);
    cudaGetSymbolAddress((void**)&p_xlo,  g_xlo);
    cudaGetSymbolAddress((void**)&p_a2hi, g_a2hi);
    cudaGetSymbolAddress((void**)&p_a2lo, g_a2lo);
    cudaGetSymbolAddress((void**)&p_B1,   g_B1);
    cudaGetSymbolAddress((void**)&p_B2,   g_B2);

    constexpr int GSMEM = 4 * TILE_B * 2;  // 81,920 bytes
    static bool attr_set = false;
    if (!attr_set) {
        cudaFuncSetAttribute(k_gemm3<256>, cudaFuncAttributeMaxDynamicSharedMemorySize, GSMEM);
        cudaFuncSetAttribute(k_gemm3<128>, cudaFuncAttributeMaxDynamicSharedMemorySize, GSMEM);
        attr_set = true;
    }

    // launches 0-2: prep
    k_split_x<<<(NN * 256 + 255) / 256, 256>>>(x);
    k_prep_w<<<(256 * 256 + 255) / 256, 256>>>(W1, p_B1, 256);
    k_prep_w<<<(256 * 128 + 255) / 256, 256>>>(W2, p_B2, 128);

    // launch 3: GEMM1 (profiled slot)
    {
        dim3 grid(2, GRID_M);
        k_gemm3<256><<<grid, 256, GSMEM>>>(p_xhi, p_xlo, p_B1, p_h1, NN);
    }

    // CSR build (independent of GEMM)
    k_init_cnt<<<(NN + 255) / 256, 256>>>();
    k_hist<<<(EE + 255) / 256, 256>>>(e_dst);
    k_scan<<<1, 1024>>>();
    k_scatter<<<(TOT_E + 255) / 256, 256>>>(e_src, e_dst);

    // Layer 1 rest
    k_alpha<<<(NN * 2 * 32 + 255) / 256, 256>>>(p_h1, a_src1, a_dst1, p_as1, p_ad1, 2);
    k_agg1<<<(NN * 32 + 255) / 256, 256>>>(b1);

    // Layer 2
    {
        dim3 grid(1, GRID_M);
        k_gemm3<128><<<grid, 256, GSMEM>>>(p_a2hi, p_a2lo, p_B2, p_h2, NN);
    }
    k_alpha<<<(NN * 32 + 255) / 256, 256>>>(p_h2, a_src2, a_dst2, p_as2, p_ad2, 1);
    k_agg2<<<(NN * 32 + 255) / 256, 256>>>(b2, out);
}

// round 5
// speedup vs baseline: 1.4528x; 1.1166x over previous
#include <cuda_runtime.h>
#include <cuda_bf16.h>
#include <cstdint>
#include <cstddef>

// Problem constants
#define NN     50000
#define EE     800000
#define TOT_E  (EE + NN)          // edges + self loops = 850000
#define INC    256
#define HIDC   128
#define OUTC   128
#define NEG_SLOPE 0.2f
#define GRID_M ((NN + 127) / 128) // 391

// ---------------------------------------------------------------------------
// Portable async-copy / mma helpers (sm_80+; safe for plain compute_100)
// ---------------------------------------------------------------------------
__device__ __forceinline__ uint32_t smem_u32(const void* p) {
    uint32_t a;
    asm("{ .reg .u64 t; cvta.to.shared.u64 t, %1; cvt.u32.u64 %0, t; }" : "=r"(a) : "l"(p));
    return a;
}
#define CP_ASYNC16(dst, src) \
    asm volatile("cp.async.cg.shared.global [%0], [%1], 16;" :: "r"(dst), "l"(src))
#define CP_COMMIT() asm volatile("cp.async.commit_group;" ::: "memory")
#define CP_WAIT1()  asm volatile("cp.async.wait_group 1;" ::: "memory")
#define CP_WAIT0()  asm volatile("cp.async.wait_group 0;" ::: "memory")

#define LDMATRIX_X4(r0, r1, r2, r3, addr) \
    asm volatile("ldmatrix.sync.aligned.m8n8.x4.shared.b16 {%0,%1,%2,%3}, [%4];" \
        : "=r"(r0), "=r"(r1), "=r"(r2), "=r"(r3) : "r"(addr))

#define MMA_BF16(c0, c1, c2, c3, a0, a1, a2, a3, b0, b1) \
    asm volatile("mma.sync.aligned.m16n8k16.row.col.f32.bf16.bf16.f32 " \
        "{%0,%1,%2,%3}, {%4,%5,%6,%7}, {%8,%9}, {%0,%1,%2,%3};" \
        : "+f"(c0), "+f"(c1), "+f"(c2), "+f"(c3) \
        : "r"(a0), "r"(a1), "r"(a2), "r"(a3), "r"(b0), "r"(b1))

// ---------------------------------------------------------------------------
// Scratch (device globals; no cudaMalloc allowed)
// ---------------------------------------------------------------------------
__device__ __align__(16) float g_h1[(size_t)NN * 256];    // layer1 linear out (fp32)
__device__ __align__(16) float g_h2[(size_t)NN * 128];    // layer2 linear out (fp32)
__device__ __align__(16) __nv_bfloat16 g_xhi[(size_t)NN * 256];
__device__ __align__(16) __nv_bfloat16 g_xlo[(size_t)NN * 256];
__device__ __align__(16) __nv_bfloat16 g_a2hi[(size_t)NN * 256];  // out1 hi
__device__ __align__(16) __nv_bfloat16 g_a2lo[(size_t)NN * 256];  // out1 lo
__device__ __align__(16) __nv_bfloat16 g_B1[256 * 512];   // W1 ext: [n][k_ext] hi|lo
__device__ __align__(16) __nv_bfloat16 g_B2[128 * 512];   // W2 ext
__device__ float g_as1[NN * 2];
__device__ float g_ad1[NN * 2];
__device__ float g_as2[NN];
__device__ float g_ad2[NN];
__device__ int   g_cnt[NN];
__device__ int   g_cur[NN];
__device__ int   g_rowptr[NN + 1];
__device__ int   g_esrc[TOT_E];

// ---------------------------------------------------------------------------
// CSR build: histogram -> scan -> scatter
// ---------------------------------------------------------------------------
__global__ void k_init_cnt() {
    int i = blockIdx.x * blockDim.x + threadIdx.x;
    if (i < NN) g_cnt[i] = 1;
}
__global__ void k_hist(const int* __restrict__ dst) {
    int i = blockIdx.x * blockDim.x + threadIdx.x;
    if (i < EE) atomicAdd(&g_cnt[dst[i]], 1);
}
__global__ void k_scan() {
    const int T = 1024;
    __shared__ int sums[T];
    int tid = threadIdx.x;
    int chunk = (NN + T - 1) / T;
    int begin = tid * chunk;
    int end   = begin + chunk; if (end > NN) end = NN;
    int s = 0;
    for (int i = begin; i < end; i++) s += g_cnt[i];
    sums[tid] = s;
    __syncthreads();
    for (int off = 1; off < T; off <<= 1) {
        int v = 0;
        if (tid >= off) v = sums[tid - off];
        __syncthreads();
        sums[tid] += v;
        __syncthreads();
    }
    int base = (tid == 0) ? 0 : sums[tid - 1];
    for (int i = begin; i < end; i++) {
        g_rowptr[i] = base;
        g_cur[i]    = base;
        base += g_cnt[i];
    }
    if (tid == T - 1) g_rowptr[NN] = base;
}
__global__ void k_scatter(const int* __restrict__ src, const int* __restrict__ dst) {
    int i = blockIdx.x * blockDim.x + threadIdx.x;
    if (i < EE) {
        int p = atomicAdd(&g_cur[dst[i]], 1);
        g_esrc[p] = src[i];
    } else if (i < TOT_E) {
        int n = i - EE;
        int p = atomicAdd(&g_cur[n], 1);
        g_esrc[p] = n;
    }
}

// ---------------------------------------------------------------------------
// Precision-split prep kernels
// ---------------------------------------------------------------------------
__global__ void k_split_x(const float* __restrict__ x) {
    size_t i = (size_t)blockIdx.x * blockDim.x + threadIdx.x;   // float4 index
    if (i >= (size_t)NN * 64) return;
    float4 v = ((const float4*)x)[i];
    __nv_bfloat16 h0 = __float2bfloat16(v.x), h1 = __float2bfloat16(v.y);
    __nv_bfloat16 h2 = __float2bfloat16(v.z), h3 = __float2bfloat16(v.w);
    __nv_bfloat162 a, b, c, d;
    a.x = h0; a.y = h1; b.x = h2; b.y = h3;
    c.x = __float2bfloat16(v.x - __bfloat162float(h0));
    c.y = __float2bfloat16(v.y - __bfloat162float(h1));
    d.x = __float2bfloat16(v.z - __bfloat162float(h2));
    d.y = __float2bfloat16(v.w - __bfloat162float(h3));
    ((__nv_bfloat162*)g_xhi)[i * 2]     = a;
    ((__nv_bfloat162*)g_xhi)[i * 2 + 1] = b;
    ((__nv_bfloat162*)g_xlo)[i * 2]     = c;
    ((__nv_bfloat162*)g_xlo)[i * 2 + 1] = d;
}
// W [K=256 rows][Ncols] fp32 -> Bext [Ncols rows][512]: cols 0..255 = hi, 256..511 = lo
__global__ void k_prep_w(const float* __restrict__ W, __nv_bfloat16* __restrict__ Bext, int Ncols) {
    int i = blockIdx.x * blockDim.x + threadIdx.x;
    if (i >= 256 * Ncols) return;
    int k = i / Ncols, n = i - k * Ncols;
    float v = W[i];
    __nv_bfloat16 h = __float2bfloat16(v);
    Bext[(size_t)n * 512 + k]       = h;
    Bext[(size_t)n * 512 + 256 + k] = __float2bfloat16(v - __bfloat162float(h));
}

// ---------------------------------------------------------------------------
// bf16x3 mma.sync GEMM, shared-tile scheme, XOR-swizzled smem, 3-stage pipe.
// Tile: 128 rows x 32 bf16 (64B rows). offset(r,chunk16) = r*64 + ((chunk ^ ((r>>1)&3))<<4).
// LDSM 8-row fetch groups hit 8 distinct 16B banks (even rows {c,c^1,c^2,c^3}, odd +4).
// ---------------------------------------------------------------------------
#define BK     32
#define TILE_B (128 * 64)          // 8192 bytes per tile
#define STAGE_B (4 * TILE_B)       // Ahi, Alo, Bhi, Blo
#define NSTAGE 3
#define NCHUNK 8                   // 256 / BK
#define SWZ(row, chunk) (((row) << 6) + ((((chunk) ^ (((row) >> 1) & 3))) << 4))

template <int NCOLS>
__global__ __launch_bounds__(256) void k_gemm3(const __nv_bfloat16* __restrict__ Ahi,
                                               const __nv_bfloat16* __restrict__ Alo,
                                               const __nv_bfloat16* __restrict__ Bext,
                                               float* __restrict__ C, int M)
{
    extern __shared__ __align__(16) char smem[];
    const uint32_t sb = smem_u32(smem);

    const int tid  = threadIdx.x;
    const int wid  = tid >> 5;
    const int lane = tid & 31;
    const int warpM = wid & 1;      // 2 x 64 rows
    const int warpN = wid >> 1;     // 4 x 32 cols
    const int rowBlock = blockIdx.y * 128;
    const int colBlock = blockIdx.x * 128;

    // loader coords: per tile, thread covers (lrow, chunks c0, c0+1)
    const int lrow = tid >> 1;            // 0..127
    const int c0   = (tid & 1) * 2;       // chunk16 index 0 or 2

    int gr = rowBlock + lrow; if (gr >= M) gr = M - 1;
    const int gn = colBlock + lrow;
    const __nv_bfloat16* aHiP = Ahi + (size_t)gr * 256 + c0 * 8;
    const __nv_bfloat16* aLoP = Alo + (size_t)gr * 256 + c0 * 8;
    const __nv_bfloat16* bHiP = Bext + (size_t)gn * 512 + c0 * 8;
    const __nv_bfloat16* bLoP = Bext + (size_t)gn * 512 + 256 + c0 * 8;
    const uint32_t w0 = SWZ(lrow, c0);
    const uint32_t w1 = SWZ(lrow, c0 + 1);

    float c[4][4][4];
#pragma unroll
    for (int i = 0; i < 4; i++)
#pragma unroll
        for (int j = 0; j < 4; j++)
#pragma unroll
            for (int q = 0; q < 4; q++) c[i][j][q] = 0.f;

    auto load_chunk = [&](int cidx) {
        const uint32_t base = sb + (cidx % NSTAGE) * STAGE_B;
        const int kin = cidx * BK;
        CP_ASYNC16(base + 0 * TILE_B + w0, aHiP + kin);
        CP_ASYNC16(base + 0 * TILE_B + w1, aHiP + kin + 8);
        CP_ASYNC16(base + 1 * TILE_B + w0, aLoP + kin);
        CP_ASYNC16(base + 1 * TILE_B + w1, aLoP + kin + 8);
        CP_ASYNC16(base + 2 * TILE_B + w0, bHiP + kin);
        CP_ASYNC16(base + 2 * TILE_B + w1, bHiP + kin + 8);
        CP_ASYNC16(base + 3 * TILE_B + w0, bLoP + kin);
        CP_ASYNC16(base + 3 * TILE_B + w1, bLoP + kin + 8);
    };

    load_chunk(0); CP_COMMIT();
    load_chunk(1); CP_COMMIT();

    for (int cidx = 0; cidx < NCHUNK; cidx++) {
        if (cidx + 1 < NCHUNK) { CP_WAIT1(); } else { CP_WAIT0(); }
        __syncthreads();
        if (cidx + 2 < NCHUNK) { load_chunk(cidx + 2); CP_COMMIT(); }

        const uint32_t stage = sb + (cidx % NSTAGE) * STAGE_B;
        const uint32_t tAhi = stage + 0 * TILE_B;
        const uint32_t tAlo = stage + 1 * TILE_B;
        const uint32_t tBhi = stage + 2 * TILE_B;
        const uint32_t tBlo = stage + 3 * TILE_B;

#pragma unroll
        for (int k16 = 0; k16 < 2; k16++) {
            const int k0 = k16 * 16;

            uint32_t bhi[8], blo[8];
#pragma unroll
            for (int np = 0; np < 2; np++) {
                const int n0 = warpN * 32 + np * 16;
                const int mat = lane >> 3;
                const int row = n0 + ((mat >> 1) << 3) + (lane & 7);
                const int col = k0 + ((mat & 1) << 3);
                const uint32_t off = SWZ(row, col >> 3);
                LDMATRIX_X4(bhi[np*4+0], bhi[np*4+1], bhi[np*4+2], bhi[np*4+3], tBhi + off);
                LDMATRIX_X4(blo[np*4+0], blo[np*4+1], blo[np*4+2], blo[np*4+3], tBlo + off);
            }
            uint32_t ahi[4][4], alo[4][4];
#pragma unroll
            for (int mt = 0; mt < 4; mt++) {
                const int m0 = warpM * 64 + mt * 16;
                const int row = m0 + (lane & 15);
                const int col = k0 + ((lane >> 4) << 3);
                const uint32_t off = SWZ(row, col >> 3);
                LDMATRIX_X4(ahi[mt][0], ahi[mt][1], ahi[mt][2], ahi[mt][3], tAhi + off);
                LDMATRIX_X4(alo[mt][0], alo[mt][1], alo[mt][2], alo[mt][3], tAlo + off);
            }
#pragma unroll
            for (int mt = 0; mt < 4; mt++) {
#pragma unroll
                for (int nt = 0; nt < 4; nt++) {
                    MMA_BF16(c[mt][nt][0], c[mt][nt][1], c[mt][nt][2], c[mt][nt][3],
                             ahi[mt][0], ahi[mt][1], ahi[mt][2], ahi[mt][3],
                             bhi[nt*2], bhi[nt*2+1]);
                    MMA_BF16(c[mt][nt][0], c[mt][nt][1], c[mt][nt][2], c[mt][nt][3],
                             alo[mt][0], alo[mt][1], alo[mt][2], alo[mt][3],
                             bhi[nt*2], bhi[nt*2+1]);
                    MMA_BF16(c[mt][nt][0], c[mt][nt][1], c[mt][nt][2], c[mt][nt][3],
                             ahi[mt][0], ahi[mt][1], ahi[mt][2], ahi[mt][3],
                             blo[nt*2], blo[nt*2+1]);
                }
            }
        }
    }

    // epilogue
#pragma unroll
    for (int mt = 0; mt < 4; mt++) {
        int r0 = rowBlock + warpM * 64 + mt * 16 + (lane >> 2);
#pragma unroll
        for (int nt = 0; nt < 4; nt++) {
            int cg = colBlock + warpN * 32 + nt * 8 + 2 * (lane & 3);
            if (r0 < M)
                *(float2*)(C + (size_t)r0 * NCOLS + cg) = make_float2(c[mt][nt][0], c[mt][nt][1]);
            if (r0 + 8 < M)
                *(float2*)(C + (size_t)(r0 + 8) * NCOLS + cg) = make_float2(c[mt][nt][2], c[mt][nt][3]);
        }
    }
}

// ---------------------------------------------------------------------------
// Alpha dot products
// ---------------------------------------------------------------------------
__device__ __forceinline__ float warp_sum(float v) {
#pragma unroll
    for (int o = 16; o; o >>= 1) v += __shfl_xor_sync(0xFFFFFFFFu, v, o);
    return v;
}
__global__ void k_alpha(const float* __restrict__ h,
                        const float* __restrict__ a_s,
                        const float* __restrict__ a_d,
                        float* __restrict__ out_s,
                        float* __restrict__ out_d,
                        int H)
{
    int g = blockIdx.x * blockDim.x + threadIdx.x;
    int w = g >> 5, lane = g & 31;
    int node = w / H, head = w - node * H;
    if (node >= NN) return;
    const float4* hv = (const float4*)(h + ((size_t)node * H + head) * 128);
    float4 x  = hv[lane];
    float4 s4 = ((const float4*)(a_s + head * 128))[lane];
    float4 d4 = ((const float4*)(a_d + head * 128))[lane];
    float ss = x.x * s4.x + x.y * s4.y + x.z * s4.z + x.w * s4.w;
    float sd = x.x * d4.x + x.y * d4.y + x.z * d4.z + x.w * d4.w;
    ss = warp_sum(ss);
    sd = warp_sum(sd);
    if (lane == 0) {
        out_s[node * H + head] = ss;
        out_d[node * H + head] = sd;
    }
}

// ---------------------------------------------------------------------------
// Aggregation (softmax folded into final divide; no max pass — scores ~N(0,1),
// exp cannot overflow; softmax is shift-invariant so result is identical)
// ---------------------------------------------------------------------------
__device__ __forceinline__ float lrelu(float x) { return x > 0.f ? x : NEG_SLOPE * x; }
__device__ __forceinline__ float eluf(float x)  { return x > 0.f ? x : (__expf(x) - 1.f); }

__device__ __forceinline__ void store4_hilo(__nv_bfloat16* hi, __nv_bfloat16* lo,
                                            size_t off, float4 v) {
    __nv_bfloat16 h0 = __float2bfloat16(v.x), h1 = __float2bfloat16(v.y);
    __nv_bfloat16 h2 = __float2bfloat16(v.z), h3 = __float2bfloat16(v.w);
    __nv_bfloat16 l0 = __float2bfloat16(v.x - __bfloat162float(h0));
    __nv_bfloat16 l1 = __float2bfloat16(v.y - __bfloat162float(h1));
    __nv_bfloat16 l2 = __float2bfloat16(v.z - __bfloat162float(h2));
    __nv_bfloat16 l3 = __float2bfloat16(v.w - __bfloat162float(h3));
    __nv_bfloat162 a, b, cc, d;
    a.x = h0; a.y = h1; b.x = h2; b.y = h3;
    cc.x = l0; cc.y = l1; d.x = l2; d.y = l3;
    *(__nv_bfloat162*)(hi + off)     = a;
    *(__nv_bfloat162*)(hi + off + 2) = b;
    *(__nv_bfloat162*)(lo + off)     = cc;
    *(__nv_bfloat162*)(lo + off + 2) = d;
}

// Layer 1: H=2, C=128/head. out1 = elu(agg + b1), stored as bf16 hi/lo for GEMM2.
__global__ __launch_bounds__(256) void k_agg1(const float* __restrict__ b1)
{
    int w = (blockIdx.x * blockDim.x + threadIdx.x) >> 5;
    int lane = threadIdx.x & 31;
    if (w >= NN) return;
    int node = w;
    int beg = g_rowptr[node], end = g_rowptr[node + 1];
    float ad0 = g_ad1[2 * node], ad1v = g_ad1[2 * node + 1];

    float4 acc0 = make_float4(0.f, 0.f, 0.f, 0.f);
    float4 acc1 = make_float4(0.f, 0.f, 0.f, 0.f);
    float d0 = 0.f, d1 = 0.f;
    const float4* hbase = (const float4*)g_h1;

    for (int t = beg; t < end; t += 32) {
        int n = end - t; if (n > 32) n = 32;
        int idx = 0; float w0 = 0.f, w1 = 0.f;
        if (lane < n) {
            idx = g_esrc[t + lane];
            float2 as = *(const float2*)&g_as1[2 * idx];
            w0 = __expf(lrelu(as.x + ad0));
            w1 = __expf(lrelu(as.y + ad1v));
        }
        d0 += w0; d1 += w1;
#pragma unroll 4
        for (int j = 0; j < n; j++) {
            int s    = __shfl_sync(0xFFFFFFFFu, idx, j);
            float u0 = __shfl_sync(0xFFFFFFFFu, w0, j);
            float u1 = __shfl_sync(0xFFFFFFFFu, w1, j);
            float4 h0 = hbase[(size_t)s * 64 + lane];
            float4 hb = hbase[(size_t)s * 64 + 32 + lane];
            acc0.x += u0 * h0.x; acc0.y += u0 * h0.y; acc0.z += u0 * h0.z; acc0.w += u0 * h0.w;
            acc1.x += u1 * hb.x; acc1.y += u1 * hb.y; acc1.z += u1 * hb.z; acc1.w += u1 * hb.w;
        }
    }
    d0 = warp_sum(d0); d1 = warp_sum(d1);
    float inv0 = 1.f / d0, inv1 = 1.f / d1;
    float4 bb0 = ((const float4*)b1)[lane];
    float4 bb1 = ((const float4*)b1)[32 + lane];
    float4 o0, o1;
    o0.x = eluf(acc0.x * inv0 + bb0.x);
    o0.y = eluf(acc0.y * inv0 + bb0.y);
    o0.z = eluf(acc0.z * inv0 + bb0.z);
    o0.w = eluf(acc0.w * inv0 + bb0.w);
    o1.x = eluf(acc1.x * inv1 + bb1.x);
    o1.y = eluf(acc1.y * inv1 + bb1.y);
    o1.z = eluf(acc1.z * inv1 + bb1.z);
    o1.w = eluf(acc1.w * inv1 + bb1.w);
    store4_hilo(g_a2hi, g_a2lo, (size_t)node * 256 + lane * 4, o0);
    store4_hilo(g_a2hi, g_a2lo, (size_t)node * 256 + 128 + lane * 4, o1);
}

// Layer 2: H=1, C=128. out = agg + b2 -> d_out.
__global__ __launch_bounds__(256) void k_agg2(const float* __restrict__ b2,
                                              float* __restrict__ out)
{
    int w = (blockIdx.x * blockDim.x + threadIdx.x) >> 5;
    int lane = threadIdx.x & 31;
    if (w >= NN) return;
    int node = w;
    int beg = g_rowptr[node], end = g_rowptr[node + 1];
    float ad = g_ad2[node];

    float4 acc = make_float4(0.f, 0.f, 0.f, 0.f);
    float d = 0.f;
    const float4* hbase = (const float4*)g_h2;

    for (int t = beg; t < end; t += 32) {
        int n = end - t; if (n > 32) n = 32;
        int idx = 0; float wv = 0.f;
        if (lane < n) {
            idx = g_esrc[t + lane];
            wv = __expf(lrelu(g_as2[idx] + ad));
        }
        d += wv;
#pragma unroll 4
        for (int j = 0; j < n; j++) {
            int s   = __shfl_sync(0xFFFFFFFFu, idx, j);
            float u = __shfl_sync(0xFFFFFFFFu, wv, j);
            float4 hv = hbase[(size_t)s * 32 + lane];
            acc.x += u * hv.x; acc.y += u * hv.y; acc.z += u * hv.z; acc.w += u * hv.w;
        }
    }
    d = warp_sum(d);
    float inv = 1.f / d;
    float4 bb = ((const float4*)b2)[lane];
    float4 o;
    o.x = acc.x * inv + bb.x;
    o.y = acc.y * inv + bb.y;
    o.z = acc.z * inv + bb.z;
    o.w = acc.w * inv + bb.w;
    ((float4*)out)[(size_t)node * 32 + lane] = o;
}

// ---------------------------------------------------------------------------
// Launch  (GEMM1 kept in the profiled slot)
// ---------------------------------------------------------------------------
extern "C" void kernel_launch(void* const* d_in, const int* in_sizes, int n_in,
                              void* d_out, int out_size)
{
    const float* x      = (const float*)d_in[0];
    const int*   eidx   = (const int*)d_in[1];
    const float* W1     = (const float*)d_in[2];
    const float* a_src1 = (const float*)d_in[3];
    const float* a_dst1 = (const float*)d_in[4];
    const float* b1     = (const float*)d_in[5];
    const float* W2     = (const float*)d_in[6];
    const float* a_src2 = (const float*)d_in[7];
    const float* a_dst2 = (const float*)d_in[8];
    const float* b2     = (const float*)d_in[9];
    float* out = (float*)d_out;

    const int* e_src = eidx;
    const int* e_dst = eidx + EE;

    float* p_h1  = nullptr; cudaGetSymbolAddress((void**)&p_h1,  g_h1);
    float* p_h2  = nullptr; cudaGetSymbolAddress((void**)&p_h2,  g_h2);
    float* p_as1 = nullptr; cudaGetSymbolAddress((void**)&p_as1, g_as1);
    float* p_ad1 = nullptr; cudaGetSymbolAddress((void**)&p_ad1, g_ad1);
    float* p_as2 = nullptr; cudaGetSymbolAddress((void**)&p_as2, g_as2);
    float* p_ad2 = nullptr; cudaGetSymbolAddress((void**)&p_ad2, g_ad2);
    __nv_bfloat16 *p_xhi, *p_xlo, *p_a2hi, *p_a2lo, *p_B1, *p_B2;
    cudaGetSymbolAddress((void**)&p_xhi,  g_xhi);
    cudaGetSymbolAddress((void**)&p_xlo,  g_xlo);
    cudaGetSymbolAddress((void**)&p_a2hi, g_a2hi);
    cudaGetSymbolAddress((void**)&p_a2lo, g_a2lo);
    cudaGetSymbolAddress((void**)&p_B1,   g_B1);
    cudaGetSymbolAddress((void**)&p_B2,   g_B2);

    constexpr int GSMEM = NSTAGE * STAGE_B;   // 98304 bytes
    static bool attr_set = false;
    if (!attr_set) {
        cudaFuncSetAttribute(k_gemm3<256>, cudaFuncAttributeMaxDynamicSharedMemorySize, GSMEM);
        cudaFuncSetAttribute(k_gemm3<128>, cudaFuncAttributeMaxDynamicSharedMemorySize, GSMEM);
        attr_set = true;
    }

    // launches 0-2: prep
    k_split_x<<<(NN * 64 + 255) / 256, 256>>>(x);
    k_prep_w<<<(256 * 256 + 255) / 256, 256>>>(W1, p_B1, 256);
    k_prep_w<<<(256 * 128 + 255) / 256, 256>>>(W2, p_B2, 128);

    // launch 3: GEMM1 (profiled slot)
    {
        dim3 grid(2, GRID_M);
        k_gemm3<256><<<grid, 256, GSMEM>>>(p_xhi, p_xlo, p_B1, p_h1, NN);
    }

    // CSR build (independent of GEMM)
    k_init_cnt<<<(NN + 255) / 256, 256>>>();
    k_hist<<<(EE + 255) / 256, 256>>>(e_dst);
    k_scan<<<1, 1024>>>();
    k_scatter<<<(TOT_E + 255) / 256, 256>>>(e_src, e_dst);

    // Layer 1 rest
    k_alpha<<<(NN * 2 * 32 + 255) / 256, 256>>>(p_h1, a_src1, a_dst1, p_as1, p_ad1, 2);
    k_agg1<<<(NN * 32 + 255) / 256, 256>>>(b1);

    // Layer 2
    {
        dim3 grid(1, GRID_M);
        k_gemm3<128><<<grid, 256, GSMEM>>>(p_a2hi, p_a2lo, p_B2, p_h2, NN);
    }
    k_alpha<<<(NN * 32 + 255) / 256, 256>>>(p_h2, a_src2, a_dst2, p_as2, p_ad2, 1);
    k_agg2<<<(NN * 32 + 255) / 256, 256>>>(b2, out);
}

// round 6
// speedup vs baseline: 1.9708x; 1.3565x over previous
#include <cuda_runtime.h>
#include <cuda_bf16.h>
#include <cuda_fp16.h>
#include <cstdint>
#include <cstddef>

// Problem constants
#define NN     50000
#define EE     800000
#define TOT_E  (EE + NN)          // edges + self loops = 850000
#define INC    256
#define HIDC   128
#define OUTC   128
#define NEG_SLOPE 0.2f
#define GRID_M ((NN + 127) / 128) // 391

// ---------------------------------------------------------------------------
// Portable async-copy / mma helpers (sm_80+; safe for plain compute_100)
// ---------------------------------------------------------------------------
__device__ __forceinline__ uint32_t smem_u32(const void* p) {
    uint32_t a;
    asm("{ .reg .u64 t; cvta.to.shared.u64 t, %1; cvt.u32.u64 %0, t; }" : "=r"(a) : "l"(p));
    return a;
}
#define CP_ASYNC16(dst, src) \
    asm volatile("cp.async.cg.shared.global [%0], [%1], 16;" :: "r"(dst), "l"(src))
#define CP_COMMIT() asm volatile("cp.async.commit_group;" ::: "memory")
#define CP_WAIT1()  asm volatile("cp.async.wait_group 1;" ::: "memory")
#define CP_WAIT0()  asm volatile("cp.async.wait_group 0;" ::: "memory")

#define LDMATRIX_X4(r0, r1, r2, r3, addr) \
    asm volatile("ldmatrix.sync.aligned.m8n8.x4.shared.b16 {%0,%1,%2,%3}, [%4];" \
        : "=r"(r0), "=r"(r1), "=r"(r2), "=r"(r3) : "r"(addr))

#define MMA_BF16(c0, c1, c2, c3, a0, a1, a2, a3, b0, b1) \
    asm volatile("mma.sync.aligned.m16n8k16.row.col.f32.bf16.bf16.f32 " \
        "{%0,%1,%2,%3}, {%4,%5,%6,%7}, {%8,%9}, {%0,%1,%2,%3};" \
        : "+f"(c0), "+f"(c1), "+f"(c2), "+f"(c3) \
        : "r"(a0), "r"(a1), "r"(a2), "r"(a3), "r"(b0), "r"(b1))

// ---------------------------------------------------------------------------
// Scratch (device globals; no cudaMalloc allowed)
// ---------------------------------------------------------------------------
__device__ __align__(16) __half g_h1[(size_t)NN * 256];   // layer1 linear out (fp16)
__device__ __align__(16) __half g_h2[(size_t)NN * 128];   // layer2 linear out (fp16)
__device__ __align__(16) __nv_bfloat16 g_xhi[(size_t)NN * 256];
__device__ __align__(16) __nv_bfloat16 g_xlo[(size_t)NN * 256];
__device__ __align__(16) __nv_bfloat16 g_a2hi[(size_t)NN * 256];  // out1 hi
__device__ __align__(16) __nv_bfloat16 g_a2lo[(size_t)NN * 256];  // out1 lo
__device__ __align__(16) __nv_bfloat16 g_B1[256 * 512];   // W1 ext: [n][k_ext] hi|lo
__device__ __align__(16) __nv_bfloat16 g_B2[128 * 512];   // W2 ext
__device__ float g_as1[NN * 2];
__device__ float g_ad1[NN * 2];
__device__ float g_as2[NN];
__device__ float g_ad2[NN];
__device__ int   g_cnt[NN];
__device__ int   g_cur[NN];
__device__ int   g_rowptr[NN + 1];
__device__ int   g_esrc[TOT_E];

// ---------------------------------------------------------------------------
// CSR build: histogram -> scan -> scatter
// ---------------------------------------------------------------------------
__global__ void k_init_cnt() {
    int i = blockIdx.x * blockDim.x + threadIdx.x;
    if (i < NN) g_cnt[i] = 1;
}
__global__ void k_hist(const int* __restrict__ dst) {
    int i = blockIdx.x * blockDim.x + threadIdx.x;
    if (i < EE) atomicAdd(&g_cnt[dst[i]], 1);
}
__global__ void k_scan() {
    const int T = 1024;
    __shared__ int sums[T];
    int tid = threadIdx.x;
    int chunk = (NN + T - 1) / T;
    int begin = tid * chunk;
    int end   = begin + chunk; if (end > NN) end = NN;
    int s = 0;
    for (int i = begin; i < end; i++) s += g_cnt[i];
    sums[tid] = s;
    __syncthreads();
    for (int off = 1; off < T; off <<= 1) {
        int v = 0;
        if (tid >= off) v = sums[tid - off];
        __syncthreads();
        sums[tid] += v;
        __syncthreads();
    }
    int base = (tid == 0) ? 0 : sums[tid - 1];
    for (int i = begin; i < end; i++) {
        g_rowptr[i] = base;
        g_cur[i]    = base;
        base += g_cnt[i];
    }
    if (tid == T - 1) g_rowptr[NN] = base;
}
__global__ void k_scatter(const int* __restrict__ src, const int* __restrict__ dst) {
    int i = blockIdx.x * blockDim.x + threadIdx.x;
    if (i < EE) {
        int p = atomicAdd(&g_cur[dst[i]], 1);
        g_esrc[p] = src[i];
    } else if (i < TOT_E) {
        int n = i - EE;
        int p = atomicAdd(&g_cur[n], 1);
        g_esrc[p] = n;
    }
}

// ---------------------------------------------------------------------------
// Precision-split prep kernels
// ---------------------------------------------------------------------------
__global__ void k_split_x(const float* __restrict__ x) {
    size_t i = (size_t)blockIdx.x * blockDim.x + threadIdx.x;   // float4 index
    if (i >= (size_t)NN * 64) return;
    float4 v = ((const float4*)x)[i];
    __nv_bfloat16 h0 = __float2bfloat16(v.x), h1 = __float2bfloat16(v.y);
    __nv_bfloat16 h2 = __float2bfloat16(v.z), h3 = __float2bfloat16(v.w);
    __nv_bfloat162 a, b, c, d;
    a.x = h0; a.y = h1; b.x = h2; b.y = h3;
    c.x = __float2bfloat16(v.x - __bfloat162float(h0));
    c.y = __float2bfloat16(v.y - __bfloat162float(h1));
    d.x = __float2bfloat16(v.z - __bfloat162float(h2));
    d.y = __float2bfloat16(v.w - __bfloat162float(h3));
    ((__nv_bfloat162*)g_xhi)[i * 2]     = a;
    ((__nv_bfloat162*)g_xhi)[i * 2 + 1] = b;
    ((__nv_bfloat162*)g_xlo)[i * 2]     = c;
    ((__nv_bfloat162*)g_xlo)[i * 2 + 1] = d;
}
// W [K=256 rows][Ncols] fp32 -> Bext [Ncols rows][512]: cols 0..255 = hi, 256..511 = lo
__global__ void k_prep_w(const float* __restrict__ W, __nv_bfloat16* __restrict__ Bext, int Ncols) {
    int i = blockIdx.x * blockDim.x + threadIdx.x;
    if (i >= 256 * Ncols) return;
    int k = i / Ncols, n = i - k * Ncols;
    float v = W[i];
    __nv_bfloat16 h = __float2bfloat16(v);
    Bext[(size_t)n * 512 + k]       = h;
    Bext[(size_t)n * 512 + 256 + k] = __float2bfloat16(v - __bfloat162float(h));
}

// ---------------------------------------------------------------------------
// bf16x3 mma.sync GEMM, shared-tile scheme, XOR-swizzled smem, 3-stage pipe.
// Output written as fp16 (gather payload precision).
// ---------------------------------------------------------------------------
#define BK     32
#define TILE_B (128 * 64)          // 8192 bytes per tile
#define STAGE_B (4 * TILE_B)       // Ahi, Alo, Bhi, Blo
#define NSTAGE 3
#define NCHUNK 8                   // 256 / BK
#define SWZ(row, chunk) (((row) << 6) + ((((chunk) ^ (((row) >> 1) & 3))) << 4))

template <int NCOLS>
__global__ __launch_bounds__(256) void k_gemm3(const __nv_bfloat16* __restrict__ Ahi,
                                               const __nv_bfloat16* __restrict__ Alo,
                                               const __nv_bfloat16* __restrict__ Bext,
                                               __half* __restrict__ C, int M)
{
    extern __shared__ __align__(16) char smem[];
    const uint32_t sb = smem_u32(smem);

    const int tid  = threadIdx.x;
    const int wid  = tid >> 5;
    const int lane = tid & 31;
    const int warpM = wid & 1;      // 2 x 64 rows
    const int warpN = wid >> 1;     // 4 x 32 cols
    const int rowBlock = blockIdx.y * 128;
    const int colBlock = blockIdx.x * 128;

    const int lrow = tid >> 1;            // 0..127
    const int c0   = (tid & 1) * 2;       // chunk16 index 0 or 2

    int gr = rowBlock + lrow; if (gr >= M) gr = M - 1;
    const int gn = colBlock + lrow;
    const __nv_bfloat16* aHiP = Ahi + (size_t)gr * 256 + c0 * 8;
    const __nv_bfloat16* aLoP = Alo + (size_t)gr * 256 + c0 * 8;
    const __nv_bfloat16* bHiP = Bext + (size_t)gn * 512 + c0 * 8;
    const __nv_bfloat16* bLoP = Bext + (size_t)gn * 512 + 256 + c0 * 8;
    const uint32_t w0 = SWZ(lrow, c0);
    const uint32_t w1 = SWZ(lrow, c0 + 1);

    float c[4][4][4];
#pragma unroll
    for (int i = 0; i < 4; i++)
#pragma unroll
        for (int j = 0; j < 4; j++)
#pragma unroll
            for (int q = 0; q < 4; q++) c[i][j][q] = 0.f;

    auto load_chunk = [&](int cidx) {
        const uint32_t base = sb + (cidx % NSTAGE) * STAGE_B;
        const int kin = cidx * BK;
        CP_ASYNC16(base + 0 * TILE_B + w0, aHiP + kin);
        CP_ASYNC16(base + 0 * TILE_B + w1, aHiP + kin + 8);
        CP_ASYNC16(base + 1 * TILE_B + w0, aLoP + kin);
        CP_ASYNC16(base + 1 * TILE_B + w1, aLoP + kin + 8);
        CP_ASYNC16(base + 2 * TILE_B + w0, bHiP + kin);
        CP_ASYNC16(base + 2 * TILE_B + w1, bHiP + kin + 8);
        CP_ASYNC16(base + 3 * TILE_B + w0, bLoP + kin);
        CP_ASYNC16(base + 3 * TILE_B + w1, bLoP + kin + 8);
    };

    load_chunk(0); CP_COMMIT();
    load_chunk(1); CP_COMMIT();

    for (int cidx = 0; cidx < NCHUNK; cidx++) {
        if (cidx + 1 < NCHUNK) { CP_WAIT1(); } else { CP_WAIT0(); }
        __syncthreads();
        if (cidx + 2 < NCHUNK) { load_chunk(cidx + 2); CP_COMMIT(); }

        const uint32_t stage = sb + (cidx % NSTAGE) * STAGE_B;
        const uint32_t tAhi = stage + 0 * TILE_B;
        const uint32_t tAlo = stage + 1 * TILE_B;
        const uint32_t tBhi = stage + 2 * TILE_B;
        const uint32_t tBlo = stage + 3 * TILE_B;

#pragma unroll
        for (int k16 = 0; k16 < 2; k16++) {
            const int k0 = k16 * 16;

            uint32_t bhi[8], blo[8];
#pragma unroll
            for (int np = 0; np < 2; np++) {
                const int n0 = warpN * 32 + np * 16;
                const int mat = lane >> 3;
                const int row = n0 + ((mat >> 1) << 3) + (lane & 7);
                const int col = k0 + ((mat & 1) << 3);
                const uint32_t off = SWZ(row, col >> 3);
                LDMATRIX_X4(bhi[np*4+0], bhi[np*4+1], bhi[np*4+2], bhi[np*4+3], tBhi + off);
                LDMATRIX_X4(blo[np*4+0], blo[np*4+1], blo[np*4+2], blo[np*4+3], tBlo + off);
            }
            uint32_t ahi[4][4], alo[4][4];
#pragma unroll
            for (int mt = 0; mt < 4; mt++) {
                const int m0 = warpM * 64 + mt * 16;
                const int row = m0 + (lane & 15);
                const int col = k0 + ((lane >> 4) << 3);
                const uint32_t off = SWZ(row, col >> 3);
                LDMATRIX_X4(ahi[mt][0], ahi[mt][1], ahi[mt][2], ahi[mt][3], tAhi + off);
                LDMATRIX_X4(alo[mt][0], alo[mt][1], alo[mt][2], alo[mt][3], tAlo + off);
            }
#pragma unroll
            for (int mt = 0; mt < 4; mt++) {
#pragma unroll
                for (int nt = 0; nt < 4; nt++) {
                    MMA_BF16(c[mt][nt][0], c[mt][nt][1], c[mt][nt][2], c[mt][nt][3],
                             ahi[mt][0], ahi[mt][1], ahi[mt][2], ahi[mt][3],
                             bhi[nt*2], bhi[nt*2+1]);
                    MMA_BF16(c[mt][nt][0], c[mt][nt][1], c[mt][nt][2], c[mt][nt][3],
                             alo[mt][0], alo[mt][1], alo[mt][2], alo[mt][3],
                             bhi[nt*2], bhi[nt*2+1]);
                    MMA_BF16(c[mt][nt][0], c[mt][nt][1], c[mt][nt][2], c[mt][nt][3],
                             ahi[mt][0], ahi[mt][1], ahi[mt][2], ahi[mt][3],
                             blo[nt*2], blo[nt*2+1]);
                }
            }
        }
    }

    // epilogue: fp32 accum -> fp16 store
#pragma unroll
    for (int mt = 0; mt < 4; mt++) {
        int r0 = rowBlock + warpM * 64 + mt * 16 + (lane >> 2);
#pragma unroll
        for (int nt = 0; nt < 4; nt++) {
            int cg = colBlock + warpN * 32 + nt * 8 + 2 * (lane & 3);
            if (r0 < M)
                *(__half2*)(C + (size_t)r0 * NCOLS + cg) =
                    __floats2half2_rn(c[mt][nt][0], c[mt][nt][1]);
            if (r0 + 8 < M)
                *(__half2*)(C + (size_t)(r0 + 8) * NCOLS + cg) =
                    __floats2half2_rn(c[mt][nt][2], c[mt][nt][3]);
        }
    }
}

// ---------------------------------------------------------------------------
// Alpha dot products (fp16 h input, fp32 math)
// ---------------------------------------------------------------------------
__device__ __forceinline__ float warp_sum(float v) {
#pragma unroll
    for (int o = 16; o; o >>= 1) v += __shfl_xor_sync(0xFFFFFFFFu, v, o);
    return v;
}
__global__ void k_alpha(const __half* __restrict__ h,
                        const float* __restrict__ a_s,
                        const float* __restrict__ a_d,
                        float* __restrict__ out_s,
                        float* __restrict__ out_d,
                        int H)
{
    int g = blockIdx.x * blockDim.x + threadIdx.x;
    int w = g >> 5, lane = g & 31;
    int node = w / H, head = w - node * H;
    if (node >= NN) return;
    const uint2* hv = (const uint2*)(h + ((size_t)node * H + head) * 128);
    uint2 u = hv[lane];
    float2 x01 = __half22float2(*(__half2*)&u.x);
    float2 x23 = __half22float2(*(__half2*)&u.y);
    float4 s4 = ((const float4*)(a_s + head * 128))[lane];
    float4 d4 = ((const float4*)(a_d + head * 128))[lane];
    float ss = x01.x * s4.x + x01.y * s4.y + x23.x * s4.z + x23.y * s4.w;
    float sd = x01.x * d4.x + x01.y * d4.y + x23.x * d4.z + x23.y * d4.w;
    ss = warp_sum(ss);
    sd = warp_sum(sd);
    if (lane == 0) {
        out_s[node * H + head] = ss;
        out_d[node * H + head] = sd;
    }
}

// ---------------------------------------------------------------------------
// Aggregation (no max pass — softmax shift-invariant, scores O(1))
// ---------------------------------------------------------------------------
__device__ __forceinline__ float lrelu(float x) { return x > 0.f ? x : NEG_SLOPE * x; }
__device__ __forceinline__ float eluf(float x)  { return x > 0.f ? x : (__expf(x) - 1.f); }

__device__ __forceinline__ void store4_hilo(__nv_bfloat16* hi, __nv_bfloat16* lo,
                                            size_t off, float4 v) {
    __nv_bfloat16 h0 = __float2bfloat16(v.x), h1 = __float2bfloat16(v.y);
    __nv_bfloat16 h2 = __float2bfloat16(v.z), h3 = __float2bfloat16(v.w);
    __nv_bfloat16 l0 = __float2bfloat16(v.x - __bfloat162float(h0));
    __nv_bfloat16 l1 = __float2bfloat16(v.y - __bfloat162float(h1));
    __nv_bfloat16 l2 = __float2bfloat16(v.z - __bfloat162float(h2));
    __nv_bfloat16 l3 = __float2bfloat16(v.w - __bfloat162float(h3));
    __nv_bfloat162 a, b, cc, d;
    a.x = h0; a.y = h1; b.x = h2; b.y = h3;
    cc.x = l0; cc.y = l1; d.x = l2; d.y = l3;
    *(__nv_bfloat162*)(hi + off)     = a;
    *(__nv_bfloat162*)(hi + off + 2) = b;
    *(__nv_bfloat162*)(lo + off)     = cc;
    *(__nv_bfloat162*)(lo + off + 2) = d;
}

// Layer 1: H=2, C=128/head. out1 = elu(agg + b1), stored as bf16 hi/lo for GEMM2.
__global__ __launch_bounds__(256) void k_agg1(const float* __restrict__ b1)
{
    int w = (blockIdx.x * blockDim.x + threadIdx.x) >> 5;
    int lane = threadIdx.x & 31;
    if (w >= NN) return;
    int node = w;
    int beg = g_rowptr[node], end = g_rowptr[node + 1];
    float ad0 = g_ad1[2 * node], ad1v = g_ad1[2 * node + 1];

    float4 acc0 = make_float4(0.f, 0.f, 0.f, 0.f);
    float4 acc1 = make_float4(0.f, 0.f, 0.f, 0.f);
    float d0 = 0.f, d1 = 0.f;
    const uint2* hbase = (const uint2*)g_h1;   // row = 64 uint2 (256 fp16)

    for (int t = beg; t < end; t += 32) {
        int n = end - t; if (n > 32) n = 32;
        int idx = 0; float w0 = 0.f, w1 = 0.f;
        if (lane < n) {
            idx = g_esrc[t + lane];
            float2 as = *(const float2*)&g_as1[2 * idx];
            w0 = __expf(lrelu(as.x + ad0));
            w1 = __expf(lrelu(as.y + ad1v));
        }
        d0 += w0; d1 += w1;
#pragma unroll 4
        for (int j = 0; j < n; j++) {
            int s    = __shfl_sync(0xFFFFFFFFu, idx, j);
            float u0 = __shfl_sync(0xFFFFFFFFu, w0, j);
            float u1 = __shfl_sync(0xFFFFFFFFu, w1, j);
            uint2 ua = hbase[(size_t)s * 64 + lane];
            uint2 ub = hbase[(size_t)s * 64 + 32 + lane];
            float2 a01 = __half22float2(*(__half2*)&ua.x);
            float2 a23 = __half22float2(*(__half2*)&ua.y);
            float2 b01 = __half22float2(*(__half2*)&ub.x);
            float2 b23 = __half22float2(*(__half2*)&ub.y);
            acc0.x += u0 * a01.x; acc0.y += u0 * a01.y; acc0.z += u0 * a23.x; acc0.w += u0 * a23.y;
            acc1.x += u1 * b01.x; acc1.y += u1 * b01.y; acc1.z += u1 * b23.x; acc1.w += u1 * b23.y;
        }
    }
    d0 = warp_sum(d0); d1 = warp_sum(d1);
    float inv0 = 1.f / d0, inv1 = 1.f / d1;
    float4 bb0 = ((const float4*)b1)[lane];
    float4 bb1 = ((const float4*)b1)[32 + lane];
    float4 o0, o1;
    o0.x = eluf(acc0.x * inv0 + bb0.x);
    o0.y = eluf(acc0.y * inv0 + bb0.y);
    o0.z = eluf(acc0.z * inv0 + bb0.z);
    o0.w = eluf(acc0.w * inv0 + bb0.w);
    o1.x = eluf(acc1.x * inv1 + bb1.x);
    o1.y = eluf(acc1.y * inv1 + bb1.y);
    o1.z = eluf(acc1.z * inv1 + bb1.z);
    o1.w = eluf(acc1.w * inv1 + bb1.w);
    store4_hilo(g_a2hi, g_a2lo, (size_t)node * 256 + lane * 4, o0);
    store4_hilo(g_a2hi, g_a2lo, (size_t)node * 256 + 128 + lane * 4, o1);
}

// Layer 2: H=1, C=128. out = agg + b2 -> d_out (fp32).
__global__ __launch_bounds__(256) void k_agg2(const float* __restrict__ b2,
                                              float* __restrict__ out)
{
    int w = (blockIdx.x * blockDim.x + threadIdx.x) >> 5;
    int lane = threadIdx.x & 31;
    if (w >= NN) return;
    int node = w;
    int beg = g_rowptr[node], end = g_rowptr[node + 1];
    float ad = g_ad2[node];

    float4 acc = make_float4(0.f, 0.f, 0.f, 0.f);
    float d = 0.f;
    const uint2* hbase = (const uint2*)g_h2;   // row = 32 uint2 (128 fp16)

    for (int t = beg; t < end; t += 32) {
        int n = end - t; if (n > 32) n = 32;
        int idx = 0; float wv = 0.f;
        if (lane < n) {
            idx = g_esrc[t + lane];
            wv = __expf(lrelu(g_as2[idx] + ad));
        }
        d += wv;
#pragma unroll 4
        for (int j = 0; j < n; j++) {
            int s   = __shfl_sync(0xFFFFFFFFu, idx, j);
            float u = __shfl_sync(0xFFFFFFFFu, wv, j);
            uint2 uv = hbase[(size_t)s * 32 + lane];
            float2 v01 = __half22float2(*(__half2*)&uv.x);
            float2 v23 = __half22float2(*(__half2*)&uv.y);
            acc.x += u * v01.x; acc.y += u * v01.y; acc.z += u * v23.x; acc.w += u * v23.y;
        }
    }
    d = warp_sum(d);
    float inv = 1.f / d;
    float4 bb = ((const float4*)b2)[lane];
    float4 o;
    o.x = acc.x * inv + bb.x;
    o.y = acc.y * inv + bb.y;
    o.z = acc.z * inv + bb.z;
    o.w = acc.w * inv + bb.w;
    ((float4*)out)[(size_t)node * 32 + lane] = o;
}

// ---------------------------------------------------------------------------
// Launch: CSR build forked onto a second stream, joined before agg1.
// ---------------------------------------------------------------------------
extern "C" void kernel_launch(void* const* d_in, const int* in_sizes, int n_in,
                              void* d_out, int out_size)
{
    const float* x      = (const float*)d_in[0];
    const int*   eidx   = (const int*)d_in[1];
    const float* W1     = (const float*)d_in[2];
    const float* a_src1 = (const float*)d_in[3];
    const float* a_dst1 = (const float*)d_in[4];
    const float* b1     = (const float*)d_in[5];
    const float* W2     = (const float*)d_in[6];
    const float* a_src2 = (const float*)d_in[7];
    const float* a_dst2 = (const float*)d_in[8];
    const float* b2     = (const float*)d_in[9];
    float* out = (float*)d_out;

    const int* e_src = eidx;
    const int* e_dst = eidx + EE;

    __half* p_h1 = nullptr; cudaGetSymbolAddress((void**)&p_h1, g_h1);
    __half* p_h2 = nullptr; cudaGetSymbolAddress((void**)&p_h2, g_h2);
    float* p_as1 = nullptr; cudaGetSymbolAddress((void**)&p_as1, g_as1);
    float* p_ad1 = nullptr; cudaGetSymbolAddress((void**)&p_ad1, g_ad1);
    float* p_as2 = nullptr; cudaGetSymbolAddress((void**)&p_as2, g_as2);
    float* p_ad2 = nullptr; cudaGetSymbolAddress((void**)&p_ad2, g_ad2);
    __nv_bfloat16 *p_xhi, *p_xlo, *p_a2hi, *p_a2lo, *p_B1, *p_B2;
    cudaGetSymbolAddress((void**)&p_xhi,  g_xhi);
    cudaGetSymbolAddress((void**)&p_xlo,  g_xlo);
    cudaGetSymbolAddress((void**)&p_a2hi, g_a2hi);
    cudaGetSymbolAddress((void**)&p_a2lo, g_a2lo);
    cudaGetSymbolAddress((void**)&p_B1,   g_B1);
    cudaGetSymbolAddress((void**)&p_B2,   g_B2);

    constexpr int GSMEM = NSTAGE * STAGE_B;   // 98304 bytes
    static cudaStream_t s2 = nullptr;
    static cudaEvent_t evFork = nullptr, evJoin = nullptr;
    if (s2 == nullptr) {
        cudaFuncSetAttribute(k_gemm3<256>, cudaFuncAttributeMaxDynamicSharedMemorySize, GSMEM);
        cudaFuncSetAttribute(k_gemm3<128>, cudaFuncAttributeMaxDynamicSharedMemorySize, GSMEM);
        cudaStreamCreateWithFlags(&s2, cudaStreamNonBlocking);
        cudaEventCreateWithFlags(&evFork, cudaEventDisableTiming);
        cudaEventCreateWithFlags(&evJoin, cudaEventDisableTiming);
    }

    // Fork: CSR build on s2, concurrent with split/prep/GEMM1/alpha1.
    cudaEventRecord(evFork, 0);
    cudaStreamWaitEvent(s2, evFork, 0);
    k_init_cnt<<<(NN + 255) / 256, 256, 0, s2>>>();
    k_hist<<<(EE + 255) / 256, 256, 0, s2>>>(e_dst);
    k_scan<<<1, 1024, 0, s2>>>();
    k_scatter<<<(TOT_E + 255) / 256, 256, 0, s2>>>(e_src, e_dst);
    cudaEventRecord(evJoin, s2);

    // Main stream: prep + GEMM1 + alpha1
    k_split_x<<<(NN * 64 + 255) / 256, 256>>>(x);
    k_prep_w<<<(256 * 256 + 255) / 256, 256>>>(W1, p_B1, 256);
    k_prep_w<<<(256 * 128 + 255) / 256, 256>>>(W2, p_B2, 128);
    {
        dim3 grid(2, GRID_M);
        k_gemm3<256><<<grid, 256, GSMEM>>>(p_xhi, p_xlo, p_B1, p_h1, NN);
    }
    k_alpha<<<(NN * 2 * 32 + 255) / 256, 256>>>(p_h1, a_src1, a_dst1, p_as1, p_ad1, 2);

    // Join: agg1 needs CSR
    cudaStreamWaitEvent(0, evJoin, 0);
    k_agg1<<<(NN * 32 + 255) / 256, 256>>>(b1);

    // Layer 2
    {
        dim3 grid(1, GRID_M);
        k_gemm3<128><<<grid, 256, GSMEM>>>(p_a2hi, p_a2lo, p_B2, p_h2, NN);
    }
    k_alpha<<<(NN * 32 + 255) / 256, 256>>>(p_h2, a_src2, a_dst2, p_as2, p_ad2, 1);
    k_agg2<<<(NN * 32 + 255) / 256, 256>>>(b2, out);
}